// round 1
// baseline (speedup 1.0000x reference)
#include <cuda_runtime.h>

#define N_TASKS   8
#define D_MODEL   1024
#define HIDDEN    1024
#define N_CLASSES 100
#define BATCH     8192

// ---------------- device scratch (no allocations allowed) ----------------
__device__ int g_count[N_TASKS];
__device__ int g_offset[N_TASKS];
__device__ int g_cursor[N_TASKS];
__device__ __align__(16) int g_rows[BATCH];                // original row ids, grouped by task
__device__ __align__(256) float g_hidden[BATCH * HIDDEN];  // layer-1 output, grouped order (32 MB)

// ---------------- grouping kernels ----------------
__global__ void reset_kernel() {
    int i = threadIdx.x;
    if (i < N_TASKS) { g_count[i] = 0; g_cursor[i] = 0; }
}

__global__ void count_kernel(const int* __restrict__ task_id) {
    int i = blockIdx.x * blockDim.x + threadIdx.x;
    if (i < BATCH) atomicAdd(&g_count[task_id[i]], 1);
}

__global__ void offset_kernel() {
    if (threadIdx.x == 0) {
        int acc = 0;
        for (int t = 0; t < N_TASKS; t++) { g_offset[t] = acc; acc += g_count[t]; }
    }
}

__global__ void scatter_kernel(const int* __restrict__ task_id) {
    int i = blockIdx.x * blockDim.x + threadIdx.x;
    if (i < BATCH) {
        int t = task_id[i];
        int pos = atomicAdd(&g_cursor[t], 1);
        g_rows[g_offset[t] + pos] = i;
    }
}

// ---------------- layer 1: h = relu(x_g @ W1[t] + b1[t]) ----------------
// grid: (HIDDEN/128, BATCH/128, N_TASKS), block 256.
// 128x128 tile, TK=16, each thread 8x8.
__global__ __launch_bounds__(256, 2)
void gemm1_kernel(const float* __restrict__ x, const float* __restrict__ W1,
                  const float* __restrict__ b1) {
    const int t   = blockIdx.z;
    const int cnt = g_count[t];
    const int m0  = blockIdx.y * 128;
    if (m0 >= cnt) return;
    const int off = g_offset[t];
    const int n0  = blockIdx.x * 128;
    const float* Wt = W1 + (size_t)t * D_MODEL * HIDDEN;

    __shared__ float As[16][128];   // [k][m]
    __shared__ float Bs[16][128];   // [k][n]
    __shared__ int   rows[128];

    const int tid = threadIdx.x;
    if (tid < 128) {
        int m = m0 + tid;
        rows[tid] = (m < cnt) ? g_rows[off + m] : -1;
    }
    __syncthreads();

    const int tx = tid & 15;   // n
    const int ty = tid >> 4;   // m

    float acc[8][8];
#pragma unroll
    for (int i = 0; i < 8; i++)
#pragma unroll
        for (int j = 0; j < 8; j++) acc[i][j] = 0.f;

    for (int kt = 0; kt < D_MODEL; kt += 16) {
        // A tile: gathered rows of x. 512 float4, 2 per thread.
#pragma unroll
        for (int q = 0; q < 2; q++) {
            int f   = tid * 2 + q;
            int row = f >> 2;            // 0..127
            int kq  = (f & 3) * 4;       // 0,4,8,12
            int r   = rows[row];
            float4 v = make_float4(0.f, 0.f, 0.f, 0.f);
            if (r >= 0)
                v = *(const float4*)(x + (size_t)r * D_MODEL + kt + kq);
            As[kq + 0][row] = v.x;
            As[kq + 1][row] = v.y;
            As[kq + 2][row] = v.z;
            As[kq + 3][row] = v.w;
        }
        // B tile: W1[t][kt+k][n0+n]. 512 float4, 2 per thread.
#pragma unroll
        for (int q = 0; q < 2; q++) {
            int f  = tid * 2 + q;
            int k  = f >> 5;             // 0..15
            int nq = (f & 31) * 4;       // 0..124
            float4 v = *(const float4*)(Wt + (size_t)(kt + k) * HIDDEN + n0 + nq);
            *(float4*)&Bs[k][nq] = v;
        }
        __syncthreads();

#pragma unroll
        for (int kk = 0; kk < 16; kk++) {
            float a[8], b[8];
#pragma unroll
            for (int i = 0; i < 8; i++) a[i] = As[kk][ty + 16 * i];
#pragma unroll
            for (int j = 0; j < 8; j++) b[j] = Bs[kk][tx + 16 * j];
#pragma unroll
            for (int i = 0; i < 8; i++)
#pragma unroll
                for (int j = 0; j < 8; j++)
                    acc[i][j] += a[i] * b[j];
        }
        __syncthreads();
    }

    // epilogue: +bias, relu, store grouped
    const float* b1t = b1 + t * HIDDEN;
#pragma unroll
    for (int i = 0; i < 8; i++) {
        int m = m0 + ty + 16 * i;
        if (m < cnt) {
            float* hrow = g_hidden + (size_t)(off + m) * HIDDEN + n0;
#pragma unroll
            for (int j = 0; j < 8; j++) {
                int n = tx + 16 * j;
                float v = acc[i][j] + b1t[n0 + n];
                hrow[n] = fmaxf(v, 0.f);
            }
        }
    }
}

// ---------------- layer 2: out = h @ W2[t] + b2[t], scatter ----------------
// grid: (1, BATCH/128, N_TASKS), block 256. N=100 padded to 128.
__global__ __launch_bounds__(256, 2)
void gemm2_kernel(const float* __restrict__ W2, const float* __restrict__ b2,
                  float* __restrict__ out) {
    const int t   = blockIdx.z;
    const int cnt = g_count[t];
    const int m0  = blockIdx.y * 128;
    if (m0 >= cnt) return;
    const int off = g_offset[t];
    const float* Wt = W2 + (size_t)t * HIDDEN * N_CLASSES;

    __shared__ float As[16][128];
    __shared__ float Bs[16][128];

    const int tid = threadIdx.x;
    const int tx = tid & 15;
    const int ty = tid >> 4;

    float acc[8][8];
#pragma unroll
    for (int i = 0; i < 8; i++)
#pragma unroll
        for (int j = 0; j < 8; j++) acc[i][j] = 0.f;

    for (int kt = 0; kt < HIDDEN; kt += 16) {
        // A: contiguous grouped hidden rows
#pragma unroll
        for (int q = 0; q < 2; q++) {
            int f   = tid * 2 + q;
            int row = f >> 2;
            int kq  = (f & 3) * 4;
            int m   = m0 + row;
            float4 v = make_float4(0.f, 0.f, 0.f, 0.f);
            if (m < cnt)
                v = *(const float4*)(g_hidden + (size_t)(off + m) * HIDDEN + kt + kq);
            As[kq + 0][row] = v.x;
            As[kq + 1][row] = v.y;
            As[kq + 2][row] = v.z;
            As[kq + 3][row] = v.w;
        }
        // B: W2[t][kt+k][n], n<100 else 0. Scalar (row stride 100 breaks alignment).
#pragma unroll
        for (int q = 0; q < 8; q++) {
            int e = q * 256 + tid;       // 0..2047, coalesced
            int k = e >> 7;              // 0..15
            int n = e & 127;             // 0..127
            Bs[k][n] = (n < N_CLASSES) ? Wt[(size_t)(kt + k) * N_CLASSES + n] : 0.f;
        }
        __syncthreads();

#pragma unroll
        for (int kk = 0; kk < 16; kk++) {
            float a[8], b[8];
#pragma unroll
            for (int i = 0; i < 8; i++) a[i] = As[kk][ty + 16 * i];
#pragma unroll
            for (int j = 0; j < 8; j++) b[j] = Bs[kk][tx + 16 * j];
#pragma unroll
            for (int i = 0; i < 8; i++)
#pragma unroll
                for (int j = 0; j < 8; j++)
                    acc[i][j] += a[i] * b[j];
        }
        __syncthreads();
    }

    const float* b2t = b2 + t * N_CLASSES;
#pragma unroll
    for (int i = 0; i < 8; i++) {
        int m = m0 + ty + 16 * i;
        if (m < cnt) {
            int r = g_rows[off + m];     // original row
#pragma unroll
            for (int j = 0; j < 8; j++) {
                int n = tx + 16 * j;
                if (n < N_CLASSES)
                    out[(size_t)r * N_CLASSES + n] = acc[i][j] + b2t[n];
            }
        }
    }
}

// ---------------- launch ----------------
extern "C" void kernel_launch(void* const* d_in, const int* in_sizes, int n_in,
                              void* d_out, int out_size) {
    const float* x       = (const float*)d_in[0];
    const int*   task_id = (const int*)d_in[1];
    const float* W1      = (const float*)d_in[2];
    const float* b1      = (const float*)d_in[3];
    const float* W2      = (const float*)d_in[4];
    const float* b2      = (const float*)d_in[5];
    float* out = (float*)d_out;

    reset_kernel<<<1, 32>>>();
    count_kernel<<<BATCH / 256, 256>>>(task_id);
    offset_kernel<<<1, 32>>>();
    scatter_kernel<<<BATCH / 256, 256>>>(task_id);

    dim3 g1(HIDDEN / 128, BATCH / 128, N_TASKS);
    gemm1_kernel<<<g1, 256>>>(x, W1, b1);

    dim3 g2(1, BATCH / 128, N_TASKS);
    gemm2_kernel<<<g2, 256>>>(W2, b2, out);
}

// round 3
// speedup vs baseline: 2.2143x; 2.2143x over previous
#include <cuda_runtime.h>
#include <cuda_bf16.h>
#include <cstdint>

#define N_TASKS   8
#define D_MODEL   1024
#define HIDDEN    1024
#define N_CLASSES 100
#define BATCH     8192
#define KEXT      3072          // 3 * 1024 (hi | lo/hi | hi/lo extension)
#define NCHUNK    96            // KEXT / 32
#define LDS       40            // smem row stride in bf16 (32 + 8 pad)

// ===================== device scratch (no allocations allowed) =====================
__device__ int g_count[N_TASKS];
__device__ int g_offset[N_TASKS];
__device__ int g_cursor[N_TASKS];
__device__ __align__(16) int g_rows[BATCH];

// A_ext for layer1: grouped x, [row][ Ahi(1024) | Alo(1024) | Ahi(1024) ]  (+128 pad rows)
__device__ __align__(256) __nv_bfloat16 g_xext[(BATCH + 128) * KEXT];
// B_ext for layer1: W1^T per task, [t][n][ Bhi | Bhi | Blo ]
__device__ __align__(256) __nv_bfloat16 g_w1ext[N_TASKS * HIDDEN * KEXT];
// B_ext for layer2: W2^T per task, n padded to 128
__device__ __align__(256) __nv_bfloat16 g_w2ext[N_TASKS * 128 * KEXT];
// A_ext for layer2: hidden activations, grouped, same extension (+128 pad rows)
__device__ __align__(256) __nv_bfloat16 g_hext[(BATCH + 128) * KEXT];

// ===================== helpers =====================
__device__ __forceinline__ uint32_t smem_u32(const void* p) {
    uint32_t a;
    asm("{ .reg .u64 t; cvta.to.shared.u64 t, %1; cvt.u32.u64 %0, t; }" : "=r"(a) : "l"(p));
    return a;
}
__device__ __forceinline__ void ldm4(uint32_t& r0, uint32_t& r1, uint32_t& r2, uint32_t& r3,
                                     uint32_t addr) {
    asm volatile("ldmatrix.sync.aligned.m8n8.x4.shared.b16 {%0,%1,%2,%3}, [%4];"
                 : "=r"(r0), "=r"(r1), "=r"(r2), "=r"(r3) : "r"(addr));
}
__device__ __forceinline__ void mma16816(float* c, const uint32_t* a, const uint32_t* b) {
    asm volatile(
        "mma.sync.aligned.m16n8k16.row.col.f32.bf16.bf16.f32 "
        "{%0,%1,%2,%3}, {%4,%5,%6,%7}, {%8,%9}, {%0,%1,%2,%3};"
        : "+f"(c[0]), "+f"(c[1]), "+f"(c[2]), "+f"(c[3])
        : "r"(a[0]), "r"(a[1]), "r"(a[2]), "r"(a[3]), "r"(b[0]), "r"(b[1]));
}
__device__ __forceinline__ void split_bf16(float f, __nv_bfloat16& h, __nv_bfloat16& l) {
    h = __float2bfloat16(f);
    l = __float2bfloat16(f - __bfloat162float(h));
}

// ===================== grouping =====================
__global__ void reset_kernel() {
    int i = threadIdx.x;
    if (i < N_TASKS) { g_count[i] = 0; g_cursor[i] = 0; }
}
__global__ void count_kernel(const int* __restrict__ task_id) {
    int i = blockIdx.x * blockDim.x + threadIdx.x;
    if (i < BATCH) atomicAdd(&g_count[task_id[i]], 1);
}
__global__ void offset_kernel() {
    if (threadIdx.x == 0) {
        int acc = 0;
        for (int t = 0; t < N_TASKS; t++) { g_offset[t] = acc; acc += g_count[t]; }
    }
}
__global__ void scatter_kernel(const int* __restrict__ task_id) {
    int i = blockIdx.x * blockDim.x + threadIdx.x;
    if (i < BATCH) {
        int t = task_id[i];
        int pos = atomicAdd(&g_cursor[t], 1);
        g_rows[g_offset[t] + pos] = i;
    }
}

// ===================== conversions =====================
// gather x by grouped row; write [hi | lo | hi]
__global__ void convert_x_kernel(const float* __restrict__ x) {
    int b = blockIdx.x;
    int r = g_rows[b];
    int tid = threadIdx.x;
    float4 v = *(const float4*)(x + (size_t)r * D_MODEL + tid * 4);
    float f[4] = {v.x, v.y, v.z, v.w};
    __nv_bfloat16 h[4], l[4];
#pragma unroll
    for (int i = 0; i < 4; i++) split_bf16(f[i], h[i], l[i]);
    size_t o = (size_t)b * KEXT + tid * 4;
    __nv_bfloat162* ph = (__nv_bfloat162*)(g_xext + o);
    ph[0] = __nv_bfloat162(h[0], h[1]); ph[1] = __nv_bfloat162(h[2], h[3]);
    __nv_bfloat162* pl = (__nv_bfloat162*)(g_xext + o + 1024);
    pl[0] = __nv_bfloat162(l[0], l[1]); pl[1] = __nv_bfloat162(l[2], l[3]);
    __nv_bfloat162* ph2 = (__nv_bfloat162*)(g_xext + o + 2048);
    ph2[0] = __nv_bfloat162(h[0], h[1]); ph2[1] = __nv_bfloat162(h[2], h[3]);
}

// W1 [t][k][n] -> [t][n][ hi | hi | lo ]
__global__ void convert_w1_kernel(const float* __restrict__ W1) {
    __shared__ float tile[32][33];
    int t = blockIdx.z, k0 = blockIdx.x * 32, n0 = blockIdx.y * 32;
    int tx = threadIdx.x, ty = threadIdx.y;
    const float* src = W1 + (size_t)t * D_MODEL * HIDDEN;
#pragma unroll
    for (int i = 0; i < 4; i++)
        tile[ty + i * 8][tx] = src[(size_t)(k0 + ty + i * 8) * HIDDEN + n0 + tx];
    __syncthreads();
#pragma unroll
    for (int i = 0; i < 4; i++) {
        int n = n0 + ty + i * 8, k = k0 + tx;
        float f = tile[tx][ty + i * 8];
        __nv_bfloat16 h, l; split_bf16(f, h, l);
        size_t o = ((size_t)t * HIDDEN + n) * KEXT + k;
        g_w1ext[o] = h; g_w1ext[o + 1024] = h; g_w1ext[o + 2048] = l;
    }
}

// W2 [t][k][100] -> [t][128][ hi | hi | lo ] (n>=100 zero)
__global__ void convert_w2_kernel(const float* __restrict__ W2) {
    __shared__ float tile[32][33];
    int t = blockIdx.z, k0 = blockIdx.x * 32, n0 = blockIdx.y * 32;
    int tx = threadIdx.x, ty = threadIdx.y;
    const float* src = W2 + (size_t)t * HIDDEN * N_CLASSES;
#pragma unroll
    for (int i = 0; i < 4; i++) {
        int n = n0 + tx;
        tile[ty + i * 8][tx] = (n < N_CLASSES)
            ? src[(size_t)(k0 + ty + i * 8) * N_CLASSES + n] : 0.f;
    }
    __syncthreads();
#pragma unroll
    for (int i = 0; i < 4; i++) {
        int n = n0 + ty + i * 8, k = k0 + tx;
        float f = tile[tx][ty + i * 8];
        __nv_bfloat16 h, l; split_bf16(f, h, l);
        size_t o = ((size_t)t * 128 + n) * KEXT + k;
        g_w2ext[o] = h; g_w2ext[o + 1024] = h; g_w2ext[o + 2048] = l;
    }
}

// ===================== GEMM core (128x128 tile over K'=3072) =====================
// smem: [p][A=0/B=1][128*LDS], double-buffered
// warps: wm = wid>>2 (2 x 64 rows), wn = wid&3 (4 x 32 cols)
// acc c[mi][ni][4]
__device__ __forceinline__ void gemm_tile_core(
    const __nv_bfloat16* __restrict__ gA,   // row 0 of this M-tile (stride KEXT)
    const __nv_bfloat16* __restrict__ gB,   // row 0 of this N-tile (stride KEXT)
    __nv_bfloat16 (*S)[2][128 * LDS],
    float c[4][4][4])
{
    const int tid  = threadIdx.x;
    const int lane = tid & 31;
    const int wid  = tid >> 5;
    const int wm   = wid >> 2;
    const int wn   = wid & 3;

    // global load mapping: 2 uint4 per thread per operand per chunk
    const int u0 = tid, u1 = 256 + tid;
    const int row0 = u0 >> 2, seg0 = u0 & 3;
    const int row1 = u1 >> 2, seg1 = u1 & 3;
    const __nv_bfloat16* gA0 = gA + (size_t)row0 * KEXT + seg0 * 8;
    const __nv_bfloat16* gA1 = gA + (size_t)row1 * KEXT + seg1 * 8;
    const __nv_bfloat16* gB0 = gB + (size_t)row0 * KEXT + seg0 * 8;
    const __nv_bfloat16* gB1 = gB + (size_t)row1 * KEXT + seg1 * 8;
    const int s0 = row0 * LDS + seg0 * 8;
    const int s1 = row1 * LDS + seg1 * 8;

    // ldmatrix address components (bytes)
    const uint32_t smem0 = smem_u32(S);
    const int rA = lane & 15, cA = (lane >> 4) * 8;           // A: row, col-elems
    const int nB = wn * 32 + ((lane >> 4) << 3) + (lane & 7); // B: n row
    const int cB = ((lane >> 3) & 1) * 8;
    uint32_t eA[4], eB[2];
#pragma unroll
    for (int mi = 0; mi < 4; mi++)
        eA[mi] = ((wm * 64 + mi * 16 + rA) * LDS + cA) * 2;
#pragma unroll
    for (int j = 0; j < 2; j++)
        eB[j] = ((nB + j * 16) * LDS + cB) * 2;

    // prologue: chunk 0 -> buffer 0
    uint4 pa0 = *(const uint4*)gA0;
    uint4 pa1 = *(const uint4*)gA1;
    uint4 pb0 = *(const uint4*)gB0;
    uint4 pb1 = *(const uint4*)gB1;
    *(uint4*)((__nv_bfloat16*)S[0][0] + s0) = pa0;
    *(uint4*)((__nv_bfloat16*)S[0][0] + s1) = pa1;
    *(uint4*)((__nv_bfloat16*)S[0][1] + s0) = pb0;
    *(uint4*)((__nv_bfloat16*)S[0][1] + s1) = pb1;
    __syncthreads();

    int p = 0;
    for (int ch = 0; ch < NCHUNK; ch++) {
        const bool more = (ch + 1 < NCHUNK);
        if (more) {
            const int kt = (ch + 1) * 32;
            pa0 = *(const uint4*)(gA0 + kt);
            pa1 = *(const uint4*)(gA1 + kt);
            pb0 = *(const uint4*)(gB0 + kt);
            pb1 = *(const uint4*)(gB1 + kt);
        }
        const uint32_t baseA = smem0 + (uint32_t)p * (2 * 128 * LDS * 2);
        const uint32_t baseB = baseA + 128 * LDS * 2;
#pragma unroll
        for (int ks = 0; ks < 2; ks++) {
            uint32_t a[4][4], b[4][2];
#pragma unroll
            for (int mi = 0; mi < 4; mi++)
                ldm4(a[mi][0], a[mi][1], a[mi][2], a[mi][3], baseA + eA[mi] + ks * 32);
#pragma unroll
            for (int j = 0; j < 2; j++) {
                uint32_t r0, r1, r2, r3;
                ldm4(r0, r1, r2, r3, baseB + eB[j] + ks * 32);
                b[2 * j][0] = r0; b[2 * j][1] = r1;
                b[2 * j + 1][0] = r2; b[2 * j + 1][1] = r3;
            }
#pragma unroll
            for (int mi = 0; mi < 4; mi++)
#pragma unroll
                for (int ni = 0; ni < 4; ni++)
                    mma16816(c[mi][ni], a[mi], b[ni]);
        }
        if (more) {
            const int q = p ^ 1;
            *(uint4*)((__nv_bfloat16*)S[q][0] + s0) = pa0;
            *(uint4*)((__nv_bfloat16*)S[q][0] + s1) = pa1;
            *(uint4*)((__nv_bfloat16*)S[q][1] + s0) = pb0;
            *(uint4*)((__nv_bfloat16*)S[q][1] + s1) = pb1;
        }
        __syncthreads();
        p ^= 1;
    }
}

// ===================== layer 1 =====================
// grid (8 ntiles, 64 mtiles, 8 tasks)
__global__ __launch_bounds__(256)
void gemm1_mma(const float* __restrict__ b1) {
    const int t   = blockIdx.z;
    const int cnt = g_count[t];
    const int m0  = blockIdx.y * 128;
    if (m0 >= cnt) return;
    const int off = g_offset[t];
    const int n0  = blockIdx.x * 128;

    __shared__ __nv_bfloat16 S[2][2][128 * LDS];
    float c[4][4][4];
#pragma unroll
    for (int mi = 0; mi < 4; mi++)
#pragma unroll
        for (int ni = 0; ni < 4; ni++)
#pragma unroll
            for (int r = 0; r < 4; r++) c[mi][ni][r] = 0.f;

    gemm_tile_core(g_xext + (size_t)(off + m0) * KEXT,
                   g_w1ext + ((size_t)t * HIDDEN + n0) * KEXT, S, c);

    const int lane = threadIdx.x & 31;
    const int wid  = threadIdx.x >> 5;
    const int wm = wid >> 2, wn = wid & 3;
    const int r4 = lane >> 2, c2 = (lane & 3) * 2;
    const float* b1t = b1 + t * HIDDEN;

#pragma unroll
    for (int mi = 0; mi < 4; mi++) {
#pragma unroll
        for (int half = 0; half < 2; half++) {
            const int m = m0 + wm * 64 + mi * 16 + r4 + half * 8;
            if (m < cnt) {
                const size_t rowo = (size_t)(off + m) * KEXT;
#pragma unroll
                for (int ni = 0; ni < 4; ni++) {
                    const int n = n0 + wn * 32 + ni * 8 + c2;
                    float v0 = fmaxf(c[mi][ni][half * 2 + 0] + b1t[n], 0.f);
                    float v1 = fmaxf(c[mi][ni][half * 2 + 1] + b1t[n + 1], 0.f);
                    __nv_bfloat16 h0, l0, h1, l1;
                    split_bf16(v0, h0, l0);
                    split_bf16(v1, h1, l1);
                    *(__nv_bfloat162*)(g_hext + rowo + n)        = __nv_bfloat162(h0, h1);
                    *(__nv_bfloat162*)(g_hext + rowo + 1024 + n) = __nv_bfloat162(l0, l1);
                    *(__nv_bfloat162*)(g_hext + rowo + 2048 + n) = __nv_bfloat162(h0, h1);
                }
            }
        }
    }
}

// ===================== layer 2 =====================
// grid (1, 64 mtiles, 8 tasks)
__global__ __launch_bounds__(256)
void gemm2_mma(const float* __restrict__ b2, float* __restrict__ out) {
    const int t   = blockIdx.z;
    const int cnt = g_count[t];
    const int m0  = blockIdx.y * 128;
    if (m0 >= cnt) return;
    const int off = g_offset[t];

    __shared__ __nv_bfloat16 S[2][2][128 * LDS];
    float c[4][4][4];
#pragma unroll
    for (int mi = 0; mi < 4; mi++)
#pragma unroll
        for (int ni = 0; ni < 4; ni++)
#pragma unroll
            for (int r = 0; r < 4; r++) c[mi][ni][r] = 0.f;

    gemm_tile_core(g_hext + (size_t)(off + m0) * KEXT,
                   g_w2ext + (size_t)t * 128 * KEXT, S, c);

    const int lane = threadIdx.x & 31;
    const int wid  = threadIdx.x >> 5;
    const int wm = wid >> 2, wn = wid & 3;
    const int r4 = lane >> 2, c2 = (lane & 3) * 2;
    const float* b2t = b2 + t * N_CLASSES;

#pragma unroll
    for (int mi = 0; mi < 4; mi++) {
#pragma unroll
        for (int half = 0; half < 2; half++) {
            const int m = m0 + wm * 64 + mi * 16 + r4 + half * 8;
            if (m < cnt) {
                const int ro = g_rows[off + m];
                float* orow = out + (size_t)ro * N_CLASSES;
#pragma unroll
                for (int ni = 0; ni < 4; ni++) {
                    const int n = wn * 32 + ni * 8 + c2;
                    if (n < N_CLASSES)
                        orow[n] = c[mi][ni][half * 2 + 0] + b2t[n];
                    if (n + 1 < N_CLASSES)
                        orow[n + 1] = c[mi][ni][half * 2 + 1] + b2t[n + 1];
                }
            }
        }
    }
}

// ===================== launch =====================
extern "C" void kernel_launch(void* const* d_in, const int* in_sizes, int n_in,
                              void* d_out, int out_size) {
    const float* x       = (const float*)d_in[0];
    const int*   task_id = (const int*)d_in[1];
    const float* W1      = (const float*)d_in[2];
    const float* b1      = (const float*)d_in[3];
    const float* W2      = (const float*)d_in[4];
    const float* b2      = (const float*)d_in[5];
    float* out = (float*)d_out;

    reset_kernel<<<1, 32>>>();
    count_kernel<<<BATCH / 256, 256>>>(task_id);
    offset_kernel<<<1, 32>>>();
    scatter_kernel<<<BATCH / 256, 256>>>(task_id);

    convert_x_kernel<<<BATCH, 256>>>(x);
    convert_w1_kernel<<<dim3(32, 32, 8), dim3(32, 8)>>>(W1);
    convert_w2_kernel<<<dim3(32, 4, 8), dim3(32, 8)>>>(W2);

    gemm1_mma<<<dim3(8, 64, 8), 256>>>(b1);
    gemm2_mma<<<dim3(1, 64, 8), 256>>>(b2, out);
}

// round 4
// speedup vs baseline: 2.2693x; 1.0248x over previous
#include <cuda_runtime.h>
#include <cuda_bf16.h>
#include <cstdint>

#define N_TASKS   8
#define D_MODEL   1024
#define HIDDEN    1024
#define N_CLASSES 100
#define BATCH     8192
#define KSTORE    2048          // [hi(1024) | lo(1024)]
#define NCHUNK    96            // 3 passes x 32 chunks of K=32
#define LDS       40            // smem row stride (bf16), conflict-free & 16B-aligned (80B)
#define STAGES    3

// ===================== device scratch =====================
__device__ int g_count[N_TASKS], g_offset[N_TASKS], g_cursor[N_TASKS];
__device__ __align__(16) int g_rows[BATCH];
__device__ __align__(256) __nv_bfloat16 g_xext[(BATCH + 128) * KSTORE];
__device__ __align__(256) __nv_bfloat16 g_w1ext[N_TASKS * HIDDEN * KSTORE];
__device__ __align__(256) __nv_bfloat16 g_w2ext[N_TASKS * 128 * KSTORE];
__device__ __align__(256) __nv_bfloat16 g_hext[(BATCH + 128) * KSTORE];

// ===================== helpers =====================
__device__ __forceinline__ uint32_t smem_u32(const void* p) {
    uint32_t a;
    asm("{ .reg .u64 t; cvta.to.shared.u64 t, %1; cvt.u32.u64 %0, t; }" : "=r"(a) : "l"(p));
    return a;
}
__device__ __forceinline__ void ldm4(uint32_t& r0, uint32_t& r1, uint32_t& r2, uint32_t& r3,
                                     uint32_t addr) {
    asm volatile("ldmatrix.sync.aligned.m8n8.x4.shared.b16 {%0,%1,%2,%3}, [%4];"
                 : "=r"(r0), "=r"(r1), "=r"(r2), "=r"(r3) : "r"(addr));
}
__device__ __forceinline__ void mma16816(float* c, const uint32_t* a, const uint32_t* b) {
    asm volatile(
        "mma.sync.aligned.m16n8k16.row.col.f32.bf16.bf16.f32 "
        "{%0,%1,%2,%3}, {%4,%5,%6,%7}, {%8,%9}, {%0,%1,%2,%3};"
        : "+f"(c[0]), "+f"(c[1]), "+f"(c[2]), "+f"(c[3])
        : "r"(a[0]), "r"(a[1]), "r"(a[2]), "r"(a[3]), "r"(b[0]), "r"(b[1]));
}
__device__ __forceinline__ void cp16(uint32_t dst, const void* src) {
    asm volatile("cp.async.cg.shared.global [%0], [%1], 16;" :: "r"(dst), "l"(src) : "memory");
}
#define CP_COMMIT() asm volatile("cp.async.commit_group;" ::: "memory")
#define CP_WAIT1()  asm volatile("cp.async.wait_group 1;" ::: "memory")
__device__ __forceinline__ void split_bf16(float f, __nv_bfloat16& h, __nv_bfloat16& l) {
    h = __float2bfloat16(f);
    l = __float2bfloat16(f - __bfloat162float(h));
}

// ===================== grouping =====================
__global__ void reset_kernel() {
    int i = threadIdx.x;
    if (i < N_TASKS) { g_count[i] = 0; g_cursor[i] = 0; }
}
__global__ void count_kernel(const int* __restrict__ task_id) {
    int i = blockIdx.x * blockDim.x + threadIdx.x;
    if (i < BATCH) atomicAdd(&g_count[task_id[i]], 1);
}
__global__ void offset_kernel() {
    if (threadIdx.x == 0) {
        int acc = 0;
        for (int t = 0; t < N_TASKS; t++) { g_offset[t] = acc; acc += g_count[t]; }
    }
}
__global__ void scatter_kernel(const int* __restrict__ task_id) {
    int i = blockIdx.x * blockDim.x + threadIdx.x;
    if (i < BATCH) {
        int t = task_id[i];
        int pos = atomicAdd(&g_cursor[t], 1);
        g_rows[g_offset[t] + pos] = i;
    }
}

// ===================== conversions =====================
__global__ void convert_x_kernel(const float* __restrict__ x) {
    int b = blockIdx.x;
    int r = g_rows[b];
    int tid = threadIdx.x;
    float4 v = *(const float4*)(x + (size_t)r * D_MODEL + tid * 4);
    float f[4] = {v.x, v.y, v.z, v.w};
    __nv_bfloat16 h[4], l[4];
#pragma unroll
    for (int i = 0; i < 4; i++) split_bf16(f[i], h[i], l[i]);
    size_t o = (size_t)b * KSTORE + tid * 4;
    __nv_bfloat162* ph = (__nv_bfloat162*)(g_xext + o);
    ph[0] = __nv_bfloat162(h[0], h[1]); ph[1] = __nv_bfloat162(h[2], h[3]);
    __nv_bfloat162* pl = (__nv_bfloat162*)(g_xext + o + 1024);
    pl[0] = __nv_bfloat162(l[0], l[1]); pl[1] = __nv_bfloat162(l[2], l[3]);
}

__global__ void convert_w1_kernel(const float* __restrict__ W1) {
    __shared__ float tile[32][33];
    int t = blockIdx.z, k0 = blockIdx.x * 32, n0 = blockIdx.y * 32;
    int tx = threadIdx.x, ty = threadIdx.y;
    const float* src = W1 + (size_t)t * D_MODEL * HIDDEN;
#pragma unroll
    for (int i = 0; i < 4; i++)
        tile[ty + i * 8][tx] = src[(size_t)(k0 + ty + i * 8) * HIDDEN + n0 + tx];
    __syncthreads();
#pragma unroll
    for (int i = 0; i < 4; i++) {
        int n = n0 + ty + i * 8, k = k0 + tx;
        float f = tile[tx][ty + i * 8];
        __nv_bfloat16 h, l; split_bf16(f, h, l);
        size_t o = ((size_t)t * HIDDEN + n) * KSTORE + k;
        g_w1ext[o] = h; g_w1ext[o + 1024] = l;
    }
}

__global__ void convert_w2_kernel(const float* __restrict__ W2) {
    __shared__ float tile[32][33];
    int t = blockIdx.z, k0 = blockIdx.x * 32, n0 = blockIdx.y * 32;
    int tx = threadIdx.x, ty = threadIdx.y;
    const float* src = W2 + (size_t)t * HIDDEN * N_CLASSES;
#pragma unroll
    for (int i = 0; i < 4; i++) {
        int n = n0 + tx;
        tile[ty + i * 8][tx] = (n < N_CLASSES)
            ? src[(size_t)(k0 + ty + i * 8) * N_CLASSES + n] : 0.f;
    }
    __syncthreads();
#pragma unroll
    for (int i = 0; i < 4; i++) {
        int n = n0 + ty + i * 8, k = k0 + tx;
        float f = tile[tx][ty + i * 8];
        __nv_bfloat16 h, l; split_bf16(f, h, l);
        size_t o = ((size_t)t * 128 + n) * KSTORE + k;
        g_w2ext[o] = h; g_w2ext[o + 1024] = l;
    }
}

// ===================== GEMM core: 128 x (NI*32) tile, cp.async 3-stage =====================
// warps: wm = wid&1 (2 x 64 rows), wn = wid>>1 (4 x NI*8 cols)
// K-chunk remap implements [Ahi|Alo|Ahi] x [Bhi|Bhi|Blo] over KSTORE=2048 arrays.
template<int NI>
__device__ __forceinline__ void gemm_core(
    const __nv_bfloat16* __restrict__ gA,
    const __nv_bfloat16* __restrict__ gB,
    char* smem, float c[4][NI][4])
{
    constexpr int BN        = NI * 32;
    constexpr int A_ELS     = 128 * LDS;
    constexpr int B_ELS     = BN * LDS;
    constexpr int STAGE_B   = (A_ELS + B_ELS) * 2;

    const int tid  = threadIdx.x;
    const int lane = tid & 31;
    const int wid  = tid >> 5;
    const int wm   = wid & 1;
    const int wn   = wid >> 1;

    const uint32_t smem0 = smem_u32(smem);

    // per-thread cp.async source/dest components
    const int rowA = tid >> 2, segA = tid & 3;  // + i*64 rows
    // ldmatrix fragment addresses (bytes, within stage)
    uint32_t eA[4], eB[NI / 2];
#pragma unroll
    for (int mi = 0; mi < 4; mi++)
        eA[mi] = ((wm * 64 + mi * 16 + (lane & 15)) * LDS + (lane >> 4) * 8) * 2;
#pragma unroll
    for (int j = 0; j < NI / 2; j++)
        eB[j] = ((wn * (BN / 4) + j * 16 + ((lane >> 4) << 3) + (lane & 7)) * LDS
                 + ((lane >> 3) & 1) * 8) * 2;

    auto issue = [&](int ch, int stage) {
        const int ka = ((ch < 64) ? ch : ch - 64) * 32;
        const int kb = ((ch < 32) ? ch : ch - 32) * 32;
        const uint32_t dA = smem0 + stage * STAGE_B;
        const uint32_t dB = dA + A_ELS * 2;
#pragma unroll
        for (int i = 0; i < 2; i++) {
            int row = rowA + i * 64;
            cp16(dA + (row * LDS + segA * 8) * 2, gA + (size_t)row * KSTORE + ka + segA * 8);
        }
#pragma unroll
        for (int i = 0; i < BN / 64; i++) {
            int row = rowA + i * 64;
            cp16(dB + (row * LDS + segA * 8) * 2, gB + (size_t)row * KSTORE + kb + segA * 8);
        }
    };

    issue(0, 0); CP_COMMIT();
    issue(1, 1); CP_COMMIT();

    for (int ch = 0; ch < NCHUNK; ch++) {
        CP_WAIT1();
        __syncthreads();
        if (ch + 2 < NCHUNK) issue(ch + 2, (ch + 2) % STAGES);
        CP_COMMIT();

        const uint32_t bA = smem0 + (ch % STAGES) * STAGE_B;
        const uint32_t bB = bA + A_ELS * 2;
#pragma unroll
        for (int ks = 0; ks < 2; ks++) {
            uint32_t a[4][4], b[NI][2];
#pragma unroll
            for (int mi = 0; mi < 4; mi++)
                ldm4(a[mi][0], a[mi][1], a[mi][2], a[mi][3], bA + eA[mi] + ks * 32);
#pragma unroll
            for (int j = 0; j < NI / 2; j++) {
                uint32_t r0, r1, r2, r3;
                ldm4(r0, r1, r2, r3, bB + eB[j] + ks * 32);
                b[2 * j][0] = r0; b[2 * j][1] = r1;
                b[2 * j + 1][0] = r2; b[2 * j + 1][1] = r3;
            }
#pragma unroll
            for (int mi = 0; mi < 4; mi++)
#pragma unroll
                for (int ni = 0; ni < NI; ni++)
                    mma16816(c[mi][ni], a[mi], b[ni]);
        }
    }
}

// ===================== layer 1: 128x256 tiles =====================
#define SMEM1 (STAGES * (128 + 256) * LDS * 2)
__global__ __launch_bounds__(256, 1)
void gemm1_mma(const float* __restrict__ b1) {
    const int t   = blockIdx.z;
    const int cnt = g_count[t];
    const int m0  = blockIdx.y * 128;
    if (m0 >= cnt) return;
    const int off = g_offset[t];
    const int n0  = blockIdx.x * 256;

    extern __shared__ char smem[];
    float c[4][8][4];
#pragma unroll
    for (int mi = 0; mi < 4; mi++)
#pragma unroll
        for (int ni = 0; ni < 8; ni++)
#pragma unroll
            for (int r = 0; r < 4; r++) c[mi][ni][r] = 0.f;

    gemm_core<8>(g_xext + (size_t)(off + m0) * KSTORE,
                 g_w1ext + ((size_t)t * HIDDEN + n0) * KSTORE, smem, c);

    const int lane = threadIdx.x & 31;
    const int wid  = threadIdx.x >> 5;
    const int wm = wid & 1, wn = wid >> 1;
    const int r4 = lane >> 2, c2 = (lane & 3) * 2;
    const float* b1t = b1 + t * HIDDEN + n0;

#pragma unroll
    for (int mi = 0; mi < 4; mi++) {
#pragma unroll
        for (int half = 0; half < 2; half++) {
            const int m = m0 + wm * 64 + mi * 16 + r4 + half * 8;
            if (m < cnt) {
                const size_t rowo = (size_t)(off + m) * KSTORE;
#pragma unroll
                for (int ni = 0; ni < 8; ni++) {
                    const int n = wn * 64 + ni * 8 + c2;
                    float v0 = fmaxf(c[mi][ni][half * 2 + 0] + b1t[n], 0.f);
                    float v1 = fmaxf(c[mi][ni][half * 2 + 1] + b1t[n + 1], 0.f);
                    __nv_bfloat16 h0, l0, h1, l1;
                    split_bf16(v0, h0, l0);
                    split_bf16(v1, h1, l1);
                    *(__nv_bfloat162*)(g_hext + rowo + n0 + n)        = __nv_bfloat162(h0, h1);
                    *(__nv_bfloat162*)(g_hext + rowo + 1024 + n0 + n) = __nv_bfloat162(l0, l1);
                }
            }
        }
    }
}

// ===================== layer 2: 128x128 tiles =====================
#define SMEM2 (STAGES * (128 + 128) * LDS * 2)
__global__ __launch_bounds__(256, 1)
void gemm2_mma(const float* __restrict__ b2, float* __restrict__ out) {
    const int t   = blockIdx.z;
    const int cnt = g_count[t];
    const int m0  = blockIdx.y * 128;
    if (m0 >= cnt) return;
    const int off = g_offset[t];

    extern __shared__ char smem[];
    float c[4][4][4];
#pragma unroll
    for (int mi = 0; mi < 4; mi++)
#pragma unroll
        for (int ni = 0; ni < 4; ni++)
#pragma unroll
            for (int r = 0; r < 4; r++) c[mi][ni][r] = 0.f;

    gemm_core<4>(g_hext + (size_t)(off + m0) * KSTORE,
                 g_w2ext + (size_t)t * 128 * KSTORE, smem, c);

    const int lane = threadIdx.x & 31;
    const int wid  = threadIdx.x >> 5;
    const int wm = wid & 1, wn = wid >> 1;
    const int r4 = lane >> 2, c2 = (lane & 3) * 2;
    const float* b2t = b2 + t * N_CLASSES;

#pragma unroll
    for (int mi = 0; mi < 4; mi++) {
#pragma unroll
        for (int half = 0; half < 2; half++) {
            const int m = m0 + wm * 64 + mi * 16 + r4 + half * 8;
            if (m < cnt) {
                const int ro = g_rows[off + m];
                float* orow = out + (size_t)ro * N_CLASSES;
#pragma unroll
                for (int ni = 0; ni < 4; ni++) {
                    const int n = wn * 32 + ni * 8 + c2;
                    if (n < N_CLASSES)
                        orow[n] = c[mi][ni][half * 2 + 0] + b2t[n];
                    if (n + 1 < N_CLASSES)
                        orow[n + 1] = c[mi][ni][half * 2 + 1] + b2t[n + 1];
                }
            }
        }
    }
}

// ===================== launch =====================
extern "C" void kernel_launch(void* const* d_in, const int* in_sizes, int n_in,
                              void* d_out, int out_size) {
    const float* x       = (const float*)d_in[0];
    const int*   task_id = (const int*)d_in[1];
    const float* W1      = (const float*)d_in[2];
    const float* b1      = (const float*)d_in[3];
    const float* W2      = (const float*)d_in[4];
    const float* b2      = (const float*)d_in[5];
    float* out = (float*)d_out;

    static bool attr_done = false;
    if (!attr_done) {
        cudaFuncSetAttribute(gemm1_mma, cudaFuncAttributeMaxDynamicSharedMemorySize, SMEM1);
        cudaFuncSetAttribute(gemm2_mma, cudaFuncAttributeMaxDynamicSharedMemorySize, SMEM2);
        attr_done = true;
    }

    reset_kernel<<<1, 32>>>();
    count_kernel<<<BATCH / 256, 256>>>(task_id);
    offset_kernel<<<1, 32>>>();
    scatter_kernel<<<BATCH / 256, 256>>>(task_id);

    convert_x_kernel<<<BATCH, 256>>>(x);
    convert_w1_kernel<<<dim3(32, 32, 8), dim3(32, 8)>>>(W1);
    convert_w2_kernel<<<dim3(32, 4, 8), dim3(32, 8)>>>(W2);

    gemm1_mma<<<dim3(4, 64, 8), 256, SMEM1>>>(b1);
    gemm2_mma<<<dim3(1, 64, 8), 256, SMEM2>>>(b2, out);
}

// round 5
// speedup vs baseline: 3.3601x; 1.4807x over previous
#include <cuda_runtime.h>
#include <cuda_fp16.h>
#include <cstdint>

#define N_TASKS   8
#define D_MODEL   1024
#define HIDDEN    1024
#define N_CLASSES 100
#define BATCH     8192
#define KA        2048          // A side: [hi(1024) | lo(1024)] fp16
#define KB        1024          // B side: fp16 weights (read twice)
#define LDS       40            // smem row stride (halves): conflict-free, 16B aligned
#define STAGES    3

// ===================== device scratch =====================
__device__ int g_count[N_TASKS], g_offset[N_TASKS], g_cursor[N_TASKS];
__device__ __align__(16) int g_rows[BATCH];
__device__ __align__(256) __half g_xh[(BATCH + 128) * KA];            // grouped x  [hi|lo]
__device__ __align__(256) __half g_w1h[N_TASKS * HIDDEN * KB];        // W1^T fp16
__device__ __align__(256) __half g_w2h[N_TASKS * 128 * KB];           // W2^T fp16 (n padded)
__device__ __align__(256) __half g_hh[(BATCH + 128) * KA];            // grouped h  [hi|lo]

// ===================== helpers =====================
__device__ __forceinline__ uint32_t smem_u32(const void* p) {
    uint32_t a;
    asm("{ .reg .u64 t; cvta.to.shared.u64 t, %1; cvt.u32.u64 %0, t; }" : "=r"(a) : "l"(p));
    return a;
}
__device__ __forceinline__ void ldm4(uint32_t& r0, uint32_t& r1, uint32_t& r2, uint32_t& r3,
                                     uint32_t addr) {
    asm volatile("ldmatrix.sync.aligned.m8n8.x4.shared.b16 {%0,%1,%2,%3}, [%4];"
                 : "=r"(r0), "=r"(r1), "=r"(r2), "=r"(r3) : "r"(addr));
}
__device__ __forceinline__ void mma16816(float* c, const uint32_t* a, const uint32_t* b) {
    asm volatile(
        "mma.sync.aligned.m16n8k16.row.col.f32.f16.f16.f32 "
        "{%0,%1,%2,%3}, {%4,%5,%6,%7}, {%8,%9}, {%0,%1,%2,%3};"
        : "+f"(c[0]), "+f"(c[1]), "+f"(c[2]), "+f"(c[3])
        : "r"(a[0]), "r"(a[1]), "r"(a[2]), "r"(a[3]), "r"(b[0]), "r"(b[1]));
}
__device__ __forceinline__ void cp16(uint32_t dst, const void* src) {
    asm volatile("cp.async.cg.shared.global [%0], [%1], 16;" :: "r"(dst), "l"(src) : "memory");
}
#define CP_COMMIT() asm volatile("cp.async.commit_group;" ::: "memory")
#define CP_WAIT1()  asm volatile("cp.async.wait_group 1;" ::: "memory")
__device__ __forceinline__ void split_h(float f, __half& h, __half& l) {
    h = __float2half(f);
    l = __float2half(f - __half2float(h));
}

// ===================== grouping =====================
__global__ void reset_kernel() {
    int i = threadIdx.x;
    if (i < N_TASKS) { g_count[i] = 0; g_cursor[i] = 0; }
}
__global__ void count_kernel(const int* __restrict__ task_id) {
    int i = blockIdx.x * blockDim.x + threadIdx.x;
    if (i < BATCH) atomicAdd(&g_count[task_id[i]], 1);
}
__global__ void offset_kernel() {
    if (threadIdx.x == 0) {
        int acc = 0;
        for (int t = 0; t < N_TASKS; t++) { g_offset[t] = acc; acc += g_count[t]; }
    }
}
__global__ void scatter_kernel(const int* __restrict__ task_id) {
    int i = blockIdx.x * blockDim.x + threadIdx.x;
    if (i < BATCH) {
        int t = task_id[i];
        int pos = atomicAdd(&g_cursor[t], 1);
        g_rows[g_offset[t] + pos] = i;
    }
}

// ===================== conversions =====================
__global__ void convert_x_kernel(const float* __restrict__ x) {
    int b = blockIdx.x;
    int r = g_rows[b];
    int tid = threadIdx.x;
    float4 v = *(const float4*)(x + (size_t)r * D_MODEL + tid * 4);
    float f[4] = {v.x, v.y, v.z, v.w};
    __half h[4], l[4];
#pragma unroll
    for (int i = 0; i < 4; i++) split_h(f[i], h[i], l[i]);
    size_t o = (size_t)b * KA + tid * 4;
    ((__half2*)(g_xh + o))[0] = __halves2half2(h[0], h[1]);
    ((__half2*)(g_xh + o))[1] = __halves2half2(h[2], h[3]);
    ((__half2*)(g_xh + o + 1024))[0] = __halves2half2(l[0], l[1]);
    ((__half2*)(g_xh + o + 1024))[1] = __halves2half2(l[2], l[3]);
}

__global__ void convert_w1_kernel(const float* __restrict__ W1) {
    __shared__ float tile[32][33];
    int t = blockIdx.z, k0 = blockIdx.x * 32, n0 = blockIdx.y * 32;
    int tx = threadIdx.x, ty = threadIdx.y;
    const float* src = W1 + (size_t)t * D_MODEL * HIDDEN;
#pragma unroll
    for (int i = 0; i < 4; i++)
        tile[ty + i * 8][tx] = src[(size_t)(k0 + ty + i * 8) * HIDDEN + n0 + tx];
    __syncthreads();
#pragma unroll
    for (int i = 0; i < 4; i++) {
        int n = n0 + ty + i * 8, k = k0 + tx;
        g_w1h[((size_t)t * HIDDEN + n) * KB + k] = __float2half(tile[tx][ty + i * 8]);
    }
}

__global__ void convert_w2_kernel(const float* __restrict__ W2) {
    __shared__ float tile[32][33];
    int t = blockIdx.z, k0 = blockIdx.x * 32, n0 = blockIdx.y * 32;
    int tx = threadIdx.x, ty = threadIdx.y;
    const float* src = W2 + (size_t)t * HIDDEN * N_CLASSES;
#pragma unroll
    for (int i = 0; i < 4; i++) {
        int n = n0 + tx;
        tile[ty + i * 8][tx] = (n < N_CLASSES)
            ? src[(size_t)(k0 + ty + i * 8) * N_CLASSES + n] : 0.f;
    }
    __syncthreads();
#pragma unroll
    for (int i = 0; i < 4; i++) {
        int n = n0 + ty + i * 8, k = k0 + tx;
        g_w2h[((size_t)t * 128 + n) * KB + k] = __float2half(tile[tx][ty + i * 8]);
    }
}

// init out with bias (layer-2 split-K accumulates atomically on top)
__global__ void init_out_kernel(const int* __restrict__ task_id,
                                const float* __restrict__ b2, float* __restrict__ out) {
    int b = blockIdx.x;
    int n = threadIdx.x;
    if (n < N_CLASSES)
        out[(size_t)b * N_CLASSES + n] = b2[task_id[b] * N_CLASSES + n];
}

// ===================== generic GEMM core =====================
// BM x BN tile, K-chunks of 32; A-chunk k = ka0 + ch*32 (stride KA array),
// B-chunk k = (ch*32) mod KB.  8 warps: wm = wid&1 (BM/2 rows), wn = wid>>1 (BN/4 cols).
template<int BM, int BN, int NCH>
__device__ __forceinline__ void gemm_core(
    const __half* __restrict__ gA, const __half* __restrict__ gB,
    int ka0, char* smem, float c[BM / 32][BN / 32][4])
{
    constexpr int MI = BM / 32, NI = BN / 32;
    constexpr int A_ELS = BM * LDS;
    constexpr int STAGE_B = (BM + BN) * LDS * 2;
    constexpr int UNITS = (BM + BN) * 4;

    const int tid  = threadIdx.x;
    const int lane = tid & 31;
    const int wid  = tid >> 5;
    const int wm   = wid & 1;
    const int wn   = wid >> 1;
    const uint32_t smem0 = smem_u32(smem);

    uint32_t eA[MI], eB[(NI + 1) / 2];
#pragma unroll
    for (int mi = 0; mi < MI; mi++)
        eA[mi] = ((wm * (BM / 2) + mi * 16 + (lane & 15)) * LDS + (lane >> 4) * 8) * 2;
#pragma unroll
    for (int j = 0; j < NI / 2; j++)
        eB[j] = ((wn * (BN / 4) + j * 16 + ((lane >> 4) << 3) + (lane & 7)) * LDS
                 + ((lane >> 3) & 1) * 8) * 2;

    auto issue = [&](int ch, int stage) {
        const int ka = ka0 + ch * 32;
        const int kb = (ch * 32) & (KB - 1);
        const uint32_t dA = smem0 + stage * STAGE_B;
        const uint32_t dB = dA + A_ELS * 2;
#pragma unroll
        for (int u = tid; u < UNITS; u += 256) {
            int row = u >> 2, seg = u & 3;
            if (row < BM)
                cp16(dA + (row * LDS + seg * 8) * 2, gA + (size_t)row * KA + ka + seg * 8);
            else {
                int r = row - BM;
                cp16(dB + (r * LDS + seg * 8) * 2, gB + (size_t)r * KB + kb + seg * 8);
            }
        }
    };

    issue(0, 0); CP_COMMIT();
    issue(1, 1); CP_COMMIT();

    for (int ch = 0; ch < NCH; ch++) {
        CP_WAIT1();
        __syncthreads();
        if (ch + 2 < NCH) issue(ch + 2, (ch + 2) % STAGES);
        CP_COMMIT();

        const uint32_t bA = smem0 + (ch % STAGES) * STAGE_B;
        const uint32_t bB = bA + A_ELS * 2;
#pragma unroll
        for (int ks = 0; ks < 2; ks++) {
            uint32_t a[MI][4], b[NI][2];
#pragma unroll
            for (int mi = 0; mi < MI; mi++)
                ldm4(a[mi][0], a[mi][1], a[mi][2], a[mi][3], bA + eA[mi] + ks * 32);
#pragma unroll
            for (int j = 0; j < NI / 2; j++) {
                uint32_t r0, r1, r2, r3;
                ldm4(r0, r1, r2, r3, bB + eB[j] + ks * 32);
                b[2 * j][0] = r0; b[2 * j][1] = r1;
                b[2 * j + 1][0] = r2; b[2 * j + 1][1] = r3;
            }
#pragma unroll
            for (int mi = 0; mi < MI; mi++)
#pragma unroll
                for (int ni = 0; ni < NI; ni++)
                    mma16816(c[mi][ni], a[mi], b[ni]);
        }
        __syncthreads();
    }
}

// ===================== layer 1: 128x128 tiles, 64 chunks =====================
#define SMEM1 (STAGES * (128 + 128) * LDS * 2)
__global__ __launch_bounds__(256)
void gemm1_mma(const float* __restrict__ b1) {
    const int t   = blockIdx.z;
    const int cnt = g_count[t];
    const int m0  = blockIdx.y * 128;
    if (m0 >= cnt) return;
    const int off = g_offset[t];
    const int n0  = blockIdx.x * 128;

    extern __shared__ char smem[];
    float c[4][4][4];
#pragma unroll
    for (int mi = 0; mi < 4; mi++)
#pragma unroll
        for (int ni = 0; ni < 4; ni++)
#pragma unroll
            for (int r = 0; r < 4; r++) c[mi][ni][r] = 0.f;

    gemm_core<128, 128, 64>(g_xh + (size_t)(off + m0) * KA,
                            g_w1h + ((size_t)t * HIDDEN + n0) * KB, 0, smem, c);

    const int lane = threadIdx.x & 31;
    const int wid  = threadIdx.x >> 5;
    const int wm = wid & 1, wn = wid >> 1;
    const int r4 = lane >> 2, c2 = (lane & 3) * 2;
    const float* b1t = b1 + t * HIDDEN + n0;

#pragma unroll
    for (int mi = 0; mi < 4; mi++) {
#pragma unroll
        for (int half = 0; half < 2; half++) {
            const int m = m0 + wm * 64 + mi * 16 + r4 + half * 8;
            if (m < cnt) {
                const size_t rowo = (size_t)(off + m) * KA;
#pragma unroll
                for (int ni = 0; ni < 4; ni++) {
                    const int n = wn * 32 + ni * 8 + c2;
                    float v0 = fmaxf(c[mi][ni][half * 2 + 0] + b1t[n], 0.f);
                    float v1 = fmaxf(c[mi][ni][half * 2 + 1] + b1t[n + 1], 0.f);
                    __half h0, l0, h1, l1;
                    split_h(v0, h0, l0);
                    split_h(v1, h1, l1);
                    *(__half2*)(g_hh + rowo + n0 + n)        = __halves2half2(h0, h1);
                    *(__half2*)(g_hh + rowo + 1024 + n0 + n) = __halves2half2(l0, l1);
                }
            }
        }
    }
}

// ===================== layer 2: 32x128 tiles, split-K=2, atomic epilogue =====================
#define SMEM2 (STAGES * (32 + 128) * LDS * 2)
__global__ __launch_bounds__(256)
void gemm2_mma(float* __restrict__ out) {
    const int t   = blockIdx.z;
    const int cnt = g_count[t];
    const int m0  = blockIdx.y * 32;
    if (m0 >= cnt) return;
    const int off = g_offset[t];
    const int ks  = blockIdx.x;          // 0: A-hi pass, 1: A-lo pass

    extern __shared__ char smem[];
    float c[1][4][4];
#pragma unroll
    for (int ni = 0; ni < 4; ni++)
#pragma unroll
        for (int r = 0; r < 4; r++) c[0][ni][r] = 0.f;

    gemm_core<32, 128, 32>(g_hh + (size_t)(off + m0) * KA,
                           g_w2h + (size_t)t * 128 * KB, ks * 1024, smem, c);

    const int lane = threadIdx.x & 31;
    const int wid  = threadIdx.x >> 5;
    const int wm = wid & 1, wn = wid >> 1;
    const int r4 = lane >> 2, c2 = (lane & 3) * 2;

#pragma unroll
    for (int half = 0; half < 2; half++) {
        const int m = m0 + wm * 16 + r4 + half * 8;
        if (m < cnt) {
            const int ro = g_rows[off + m];
            float* orow = out + (size_t)ro * N_CLASSES;
#pragma unroll
            for (int ni = 0; ni < 4; ni++) {
                const int n = wn * 32 + ni * 8 + c2;
                if (n < N_CLASSES)
                    atomicAdd(orow + n, c[0][ni][half * 2 + 0]);
                if (n + 1 < N_CLASSES)
                    atomicAdd(orow + n + 1, c[0][ni][half * 2 + 1]);
            }
        }
    }
}

// ===================== launch =====================
extern "C" void kernel_launch(void* const* d_in, const int* in_sizes, int n_in,
                              void* d_out, int out_size) {
    const float* x       = (const float*)d_in[0];
    const int*   task_id = (const int*)d_in[1];
    const float* W1      = (const float*)d_in[2];
    const float* b1      = (const float*)d_in[3];
    const float* W2      = (const float*)d_in[4];
    const float* b2      = (const float*)d_in[5];
    float* out = (float*)d_out;

    static bool attr_done = false;
    if (!attr_done) {
        cudaFuncSetAttribute(gemm1_mma, cudaFuncAttributeMaxDynamicSharedMemorySize, SMEM1);
        cudaFuncSetAttribute(gemm2_mma, cudaFuncAttributeMaxDynamicSharedMemorySize, SMEM2);
        attr_done = true;
    }

    reset_kernel<<<1, 32>>>();
    count_kernel<<<BATCH / 256, 256>>>(task_id);
    offset_kernel<<<1, 32>>>();
    scatter_kernel<<<BATCH / 256, 256>>>(task_id);

    convert_x_kernel<<<BATCH, 256>>>(x);
    convert_w1_kernel<<<dim3(32, 32, 8), dim3(32, 8)>>>(W1);
    convert_w2_kernel<<<dim3(32, 4, 8), dim3(32, 8)>>>(W2);
    init_out_kernel<<<BATCH, 128>>>(task_id, b2, out);

    gemm1_mma<<<dim3(8, 64, 8), 256, SMEM1>>>(b1);
    gemm2_mma<<<dim3(2, 256, 8), 256, SMEM2>>>(out);
}

// round 6
// speedup vs baseline: 6.0487x; 1.8002x over previous
#include <cuda_runtime.h>
#include <cuda_fp16.h>
#include <cstdint>

#define N_TASKS   8
#define D_MODEL   1024
#define HIDDEN    1024
#define N_CLASSES 100
#define BATCH     8192
#define KDIM      1024
#define LDS       40            // smem row stride (halves): conflict-free, 16B aligned
#define STAGES    3

// ===================== device scratch =====================
__device__ int g_count[N_TASKS], g_offset[N_TASKS];
__device__ __align__(16) int g_rows[BATCH];
__device__ __align__(256) __half g_xh[(BATCH + 128) * KDIM];      // grouped x, fp16
__device__ __align__(256) __half g_w1h[N_TASKS * HIDDEN * KDIM];  // W1^T fp16
__device__ __align__(256) __half g_w2h[N_TASKS * 128 * KDIM];     // W2^T fp16 (n padded)
__device__ __align__(256) __half g_hh[(BATCH + 128) * KDIM];      // grouped h, fp16

// ===================== helpers =====================
__device__ __forceinline__ uint32_t smem_u32(const void* p) {
    uint32_t a;
    asm("{ .reg .u64 t; cvta.to.shared.u64 t, %1; cvt.u32.u64 %0, t; }" : "=r"(a) : "l"(p));
    return a;
}
__device__ __forceinline__ void ldm4(uint32_t& r0, uint32_t& r1, uint32_t& r2, uint32_t& r3,
                                     uint32_t addr) {
    asm volatile("ldmatrix.sync.aligned.m8n8.x4.shared.b16 {%0,%1,%2,%3}, [%4];"
                 : "=r"(r0), "=r"(r1), "=r"(r2), "=r"(r3) : "r"(addr));
}
__device__ __forceinline__ void mma16816(float* c, const uint32_t* a, const uint32_t* b) {
    asm volatile(
        "mma.sync.aligned.m16n8k16.row.col.f32.f16.f16.f32 "
        "{%0,%1,%2,%3}, {%4,%5,%6,%7}, {%8,%9}, {%0,%1,%2,%3};"
        : "+f"(c[0]), "+f"(c[1]), "+f"(c[2]), "+f"(c[3])
        : "r"(a[0]), "r"(a[1]), "r"(a[2]), "r"(a[3]), "r"(b[0]), "r"(b[1]));
}
__device__ __forceinline__ void cp16(uint32_t dst, const void* src) {
    asm volatile("cp.async.cg.shared.global [%0], [%1], 16;" :: "r"(dst), "l"(src) : "memory");
}
#define CP_COMMIT() asm volatile("cp.async.commit_group;" ::: "memory")
#define CP_WAIT1()  asm volatile("cp.async.wait_group 1;" ::: "memory")

// ===================== fused grouping: ONE kernel, one CTA =====================
__global__ __launch_bounds__(1024)
void group_kernel(const int* __restrict__ task_id) {
    __shared__ int cnt[N_TASKS], offs[N_TASKS], cur[N_TASKS];
    const int tid = threadIdx.x;
    if (tid < N_TASKS) { cnt[tid] = 0; cur[tid] = 0; }
    __syncthreads();
    int ids[8];
#pragma unroll
    for (int i = 0; i < 8; i++) {
        ids[i] = task_id[tid * 8 + i];
        atomicAdd(&cnt[ids[i]], 1);
    }
    __syncthreads();
    if (tid == 0) {
        int a = 0;
        for (int t = 0; t < N_TASKS; t++) {
            offs[t] = a; g_offset[t] = a; g_count[t] = cnt[t]; a += cnt[t];
        }
    }
    __syncthreads();
#pragma unroll
    for (int i = 0; i < 8; i++) {
        int t = ids[i];
        int p = atomicAdd(&cur[t], 1);
        g_rows[offs[t] + p] = tid * 8 + i;
    }
}

// ===================== conversions =====================
__global__ void convert_x_kernel(const float* __restrict__ x) {
    int b = blockIdx.x;
    int r = g_rows[b];
    int tid = threadIdx.x;
    float4 v = *(const float4*)(x + (size_t)r * D_MODEL + tid * 4);
    size_t o = (size_t)b * KDIM + tid * 4;
    ((__half2*)(g_xh + o))[0] = __halves2half2(__float2half(v.x), __float2half(v.y));
    ((__half2*)(g_xh + o))[1] = __halves2half2(__float2half(v.z), __float2half(v.w));
}

__global__ void convert_w1_kernel(const float* __restrict__ W1) {
    __shared__ float tile[32][33];
    int t = blockIdx.z, k0 = blockIdx.x * 32, n0 = blockIdx.y * 32;
    int tx = threadIdx.x, ty = threadIdx.y;
    const float* src = W1 + (size_t)t * D_MODEL * HIDDEN;
#pragma unroll
    for (int i = 0; i < 4; i++)
        tile[ty + i * 8][tx] = src[(size_t)(k0 + ty + i * 8) * HIDDEN + n0 + tx];
    __syncthreads();
#pragma unroll
    for (int i = 0; i < 4; i++) {
        int n = n0 + ty + i * 8, k = k0 + tx;
        g_w1h[((size_t)t * HIDDEN + n) * KDIM + k] = __float2half(tile[tx][ty + i * 8]);
    }
}

__global__ void convert_w2_kernel(const float* __restrict__ W2) {
    __shared__ float tile[32][33];
    int t = blockIdx.z, k0 = blockIdx.x * 32, n0 = blockIdx.y * 32;
    int tx = threadIdx.x, ty = threadIdx.y;
    const float* src = W2 + (size_t)t * HIDDEN * N_CLASSES;
#pragma unroll
    for (int i = 0; i < 4; i++) {
        int n = n0 + tx;
        tile[ty + i * 8][tx] = (n < N_CLASSES)
            ? src[(size_t)(k0 + ty + i * 8) * N_CLASSES + n] : 0.f;
    }
    __syncthreads();
#pragma unroll
    for (int i = 0; i < 4; i++) {
        int n = n0 + ty + i * 8, k = k0 + tx;
        g_w2h[((size_t)t * 128 + n) * KDIM + k] = __float2half(tile[tx][ty + i * 8]);
    }
}

// ===================== GEMM core: BM x BN tile, K=1024, 32-wide chunks =====================
// 8 warps: wm = wid&1 (BM/2 rows), wn = wid>>1 (BN/4 cols)
template<int BM, int BN>
__device__ __forceinline__ void gemm_core(
    const __half* __restrict__ gA, const __half* __restrict__ gB,
    char* smem, float c[BM / 32][BN / 32][4])
{
    constexpr int MI = BM / 32, NI = BN / 32;
    constexpr int NCH = KDIM / 32;
    constexpr int A_ELS = BM * LDS;
    constexpr int STAGE_B = (BM + BN) * LDS * 2;
    constexpr int UNITS = (BM + BN) * 4;

    const int tid  = threadIdx.x;
    const int lane = tid & 31;
    const int wid  = tid >> 5;
    const int wm   = wid & 1;
    const int wn   = wid >> 1;
    const uint32_t smem0 = smem_u32(smem);

    uint32_t eA[MI], eB[NI / 2];
#pragma unroll
    for (int mi = 0; mi < MI; mi++)
        eA[mi] = ((wm * (BM / 2) + mi * 16 + (lane & 15)) * LDS + (lane >> 4) * 8) * 2;
#pragma unroll
    for (int j = 0; j < NI / 2; j++)
        eB[j] = ((wn * (BN / 4) + j * 16 + ((lane >> 4) << 3) + (lane & 7)) * LDS
                 + ((lane >> 3) & 1) * 8) * 2;

    auto issue = [&](int ch, int stage) {
        const int k = ch * 32;
        const uint32_t dA = smem0 + stage * STAGE_B;
        const uint32_t dB = dA + A_ELS * 2;
#pragma unroll
        for (int u = tid; u < UNITS; u += 256) {
            int row = u >> 2, seg = u & 3;
            if (row < BM)
                cp16(dA + (row * LDS + seg * 8) * 2, gA + (size_t)row * KDIM + k + seg * 8);
            else {
                int r = row - BM;
                cp16(dB + (r * LDS + seg * 8) * 2, gB + (size_t)r * KDIM + k + seg * 8);
            }
        }
    };

    issue(0, 0); CP_COMMIT();
    issue(1, 1); CP_COMMIT();

    for (int ch = 0; ch < NCH; ch++) {
        CP_WAIT1();
        __syncthreads();
        if (ch + 2 < NCH) issue(ch + 2, (ch + 2) % STAGES);
        CP_COMMIT();

        const uint32_t bA = smem0 + (ch % STAGES) * STAGE_B;
        const uint32_t bB = bA + A_ELS * 2;
#pragma unroll
        for (int ks = 0; ks < 2; ks++) {
            uint32_t a[MI][4], b[NI][2];
#pragma unroll
            for (int mi = 0; mi < MI; mi++)
                ldm4(a[mi][0], a[mi][1], a[mi][2], a[mi][3], bA + eA[mi] + ks * 32);
#pragma unroll
            for (int j = 0; j < NI / 2; j++) {
                uint32_t r0, r1, r2, r3;
                ldm4(r0, r1, r2, r3, bB + eB[j] + ks * 32);
                b[2 * j][0] = r0; b[2 * j][1] = r1;
                b[2 * j + 1][0] = r2; b[2 * j + 1][1] = r3;
            }
#pragma unroll
            for (int mi = 0; mi < MI; mi++)
#pragma unroll
                for (int ni = 0; ni < NI; ni++)
                    mma16816(c[mi][ni], a[mi], b[ni]);
        }
    }
}

// ===================== layer 1: 128x128 tiles =====================
#define SMEM1 (STAGES * (128 + 128) * LDS * 2)
__global__ __launch_bounds__(256, 2)
void gemm1_mma(const float* __restrict__ b1) {
    const int t   = blockIdx.z;
    const int cnt = g_count[t];
    const int m0  = blockIdx.y * 128;
    if (m0 >= cnt) return;
    const int off = g_offset[t];
    const int n0  = blockIdx.x * 128;

    extern __shared__ char smem[];
    float c[4][4][4];
#pragma unroll
    for (int mi = 0; mi < 4; mi++)
#pragma unroll
        for (int ni = 0; ni < 4; ni++)
#pragma unroll
            for (int r = 0; r < 4; r++) c[mi][ni][r] = 0.f;

    gemm_core<128, 128>(g_xh + (size_t)(off + m0) * KDIM,
                        g_w1h + ((size_t)t * HIDDEN + n0) * KDIM, smem, c);

    const int lane = threadIdx.x & 31;
    const int wid  = threadIdx.x >> 5;
    const int wm = wid & 1, wn = wid >> 1;
    const int r4 = lane >> 2, c2 = (lane & 3) * 2;
    const float* b1t = b1 + t * HIDDEN + n0;

#pragma unroll
    for (int mi = 0; mi < 4; mi++) {
#pragma unroll
        for (int half = 0; half < 2; half++) {
            const int m = m0 + wm * 64 + mi * 16 + r4 + half * 8;
            if (m < cnt) {
                const size_t rowo = (size_t)(off + m) * KDIM;
#pragma unroll
                for (int ni = 0; ni < 4; ni++) {
                    const int n = wn * 32 + ni * 8 + c2;
                    float v0 = fmaxf(c[mi][ni][half * 2 + 0] + b1t[n], 0.f);
                    float v1 = fmaxf(c[mi][ni][half * 2 + 1] + b1t[n + 1], 0.f);
                    *(__half2*)(g_hh + rowo + n0 + n) =
                        __halves2half2(__float2half(v0), __float2half(v1));
                }
            }
        }
    }
}

// ===================== layer 2: 32x128 tiles, direct store + bias =====================
#define SMEM2 (STAGES * (32 + 128) * LDS * 2)
__global__ __launch_bounds__(256, 2)
void gemm2_mma(const float* __restrict__ b2, float* __restrict__ out) {
    const int t   = blockIdx.z;
    const int cnt = g_count[t];
    const int m0  = blockIdx.y * 32;
    if (m0 >= cnt) return;
    const int off = g_offset[t];

    extern __shared__ char smem[];
    float c[1][4][4];
#pragma unroll
    for (int ni = 0; ni < 4; ni++)
#pragma unroll
        for (int r = 0; r < 4; r++) c[0][ni][r] = 0.f;

    gemm_core<32, 128>(g_hh + (size_t)(off + m0) * KDIM,
                       g_w2h + (size_t)t * 128 * KDIM, smem, c);

    const int lane = threadIdx.x & 31;
    const int wid  = threadIdx.x >> 5;
    const int wm = wid & 1, wn = wid >> 1;
    const int r4 = lane >> 2, c2 = (lane & 3) * 2;
    const float* b2t = b2 + t * N_CLASSES;

#pragma unroll
    for (int half = 0; half < 2; half++) {
        const int m = m0 + wm * 16 + r4 + half * 8;
        if (m < cnt) {
            const int ro = g_rows[off + m];
            float* orow = out + (size_t)ro * N_CLASSES;
#pragma unroll
            for (int ni = 0; ni < 4; ni++) {
                const int n = wn * 32 + ni * 8 + c2;
                if (n < N_CLASSES)
                    orow[n] = c[0][ni][half * 2 + 0] + b2t[n];
                if (n + 1 < N_CLASSES)
                    orow[n + 1] = c[0][ni][half * 2 + 1] + b2t[n + 1];
            }
        }
    }
}

// ===================== launch =====================
extern "C" void kernel_launch(void* const* d_in, const int* in_sizes, int n_in,
                              void* d_out, int out_size) {
    const float* x       = (const float*)d_in[0];
    const int*   task_id = (const int*)d_in[1];
    const float* W1      = (const float*)d_in[2];
    const float* b1      = (const float*)d_in[3];
    const float* W2      = (const float*)d_in[4];
    const float* b2      = (const float*)d_in[5];
    float* out = (float*)d_out;

    static bool attr_done = false;
    if (!attr_done) {
        cudaFuncSetAttribute(gemm1_mma, cudaFuncAttributeMaxDynamicSharedMemorySize, SMEM1);
        cudaFuncSetAttribute(gemm2_mma, cudaFuncAttributeMaxDynamicSharedMemorySize, SMEM2);
        attr_done = true;
    }

    group_kernel<<<1, 1024>>>(task_id);
    convert_w1_kernel<<<dim3(32, 32, 8), dim3(32, 8)>>>(W1);
    convert_w2_kernel<<<dim3(32, 4, 8), dim3(32, 8)>>>(W2);
    convert_x_kernel<<<BATCH, 256>>>(x);

    gemm1_mma<<<dim3(8, 64, 8), 256, SMEM1>>>(b1);
    gemm2_mma<<<dim3(1, 256, 8), 256, SMEM2>>>(b2, out);
}

// round 8
// speedup vs baseline: 6.1513x; 1.0170x over previous
#include <cuda_runtime.h>
#include <cuda_fp16.h>
#include <cstdint>

#define N_TASKS   8
#define D_MODEL   1024
#define HIDDEN    1024
#define N_CLASSES 100
#define BATCH     8192
#define KDIM      1024
#define LDSA      72            // A smem row stride (halves): 64 + 8
#define LDSB      136           // B smem row stride (halves): 128 + 8
#define STAGES    3

// ===================== device scratch =====================
__device__ int g_count[N_TASKS], g_offset[N_TASKS];
__device__ __align__(16) int g_rows[BATCH];
__device__ __align__(256) __half g_xh[(BATCH + 128) * KDIM];      // grouped x, fp16 [m][k]
__device__ __align__(256) __half g_w1h[N_TASKS * KDIM * HIDDEN];  // W1 fp16, native [t][k][n]
__device__ __align__(256) __half g_w2h[N_TASKS * KDIM * 128];     // W2 fp16 [t][k][n pad 128]
__device__ __align__(256) __half g_hh[(BATCH + 128) * KDIM];      // grouped h, fp16 [m][k]

// ===================== helpers =====================
__device__ __forceinline__ uint32_t smem_u32(const void* p) {
    uint32_t a;
    asm("{ .reg .u64 t; cvta.to.shared.u64 t, %1; cvt.u32.u64 %0, t; }" : "=r"(a) : "l"(p));
    return a;
}
__device__ __forceinline__ void ldm4(uint32_t& r0, uint32_t& r1, uint32_t& r2, uint32_t& r3,
                                     uint32_t addr) {
    asm volatile("ldmatrix.sync.aligned.m8n8.x4.shared.b16 {%0,%1,%2,%3}, [%4];"
                 : "=r"(r0), "=r"(r1), "=r"(r2), "=r"(r3) : "r"(addr));
}
__device__ __forceinline__ void ldm4t(uint32_t& r0, uint32_t& r1, uint32_t& r2, uint32_t& r3,
                                      uint32_t addr) {
    asm volatile("ldmatrix.sync.aligned.m8n8.x4.trans.shared.b16 {%0,%1,%2,%3}, [%4];"
                 : "=r"(r0), "=r"(r1), "=r"(r2), "=r"(r3) : "r"(addr));
}
__device__ __forceinline__ void mma16816(float* c, const uint32_t* a, const uint32_t* b) {
    asm volatile(
        "mma.sync.aligned.m16n8k16.row.col.f32.f16.f16.f32 "
        "{%0,%1,%2,%3}, {%4,%5,%6,%7}, {%8,%9}, {%0,%1,%2,%3};"
        : "+f"(c[0]), "+f"(c[1]), "+f"(c[2]), "+f"(c[3])
        : "r"(a[0]), "r"(a[1]), "r"(a[2]), "r"(a[3]), "r"(b[0]), "r"(b[1]));
}
__device__ __forceinline__ void cp16(uint32_t dst, const void* src) {
    asm volatile("cp.async.cg.shared.global [%0], [%1], 16;" :: "r"(dst), "l"(src) : "memory");
}
#define CP_COMMIT() asm volatile("cp.async.commit_group;" ::: "memory")
#define CP_WAIT1()  asm volatile("cp.async.wait_group 1;" ::: "memory")

// ===================== fused grouping: one CTA =====================
__global__ __launch_bounds__(1024)
void group_kernel(const int* __restrict__ task_id) {
    __shared__ int cnt[N_TASKS], offs[N_TASKS], cur[N_TASKS];
    const int tid = threadIdx.x;
    if (tid < N_TASKS) { cnt[tid] = 0; cur[tid] = 0; }
    __syncthreads();
    int ids[8];
#pragma unroll
    for (int i = 0; i < 8; i++) {
        ids[i] = task_id[tid * 8 + i];
        atomicAdd(&cnt[ids[i]], 1);
    }
    __syncthreads();
    if (tid == 0) {
        int a = 0;
        for (int t = 0; t < N_TASKS; t++) {
            offs[t] = a; g_offset[t] = a; g_count[t] = cnt[t]; a += cnt[t];
        }
    }
    __syncthreads();
#pragma unroll
    for (int i = 0; i < 8; i++) {
        int t = ids[i];
        int p = atomicAdd(&cur[t], 1);
        g_rows[offs[t] + p] = tid * 8 + i;
    }
}

// ===================== conversions =====================
// gather x: 4 rows per block, 16 floats per thread (MLP 4)
__global__ void convert_x_kernel(const float* __restrict__ x) {
    const int lrow = threadIdx.x >> 6;           // 0..3
    const int j    = threadIdx.x & 63;
    const int b    = blockIdx.x * 4 + lrow;
    const int r    = g_rows[b];
    const float* src = x + (size_t)r * D_MODEL + j * 16;
    float4 v0 = ((const float4*)src)[0];
    float4 v1 = ((const float4*)src)[1];
    float4 v2 = ((const float4*)src)[2];
    float4 v3 = ((const float4*)src)[3];
    __half2 o[8];
    o[0] = __halves2half2(__float2half(v0.x), __float2half(v0.y));
    o[1] = __halves2half2(__float2half(v0.z), __float2half(v0.w));
    o[2] = __halves2half2(__float2half(v1.x), __float2half(v1.y));
    o[3] = __halves2half2(__float2half(v1.z), __float2half(v1.w));
    o[4] = __halves2half2(__float2half(v2.x), __float2half(v2.y));
    o[5] = __halves2half2(__float2half(v2.z), __float2half(v2.w));
    o[6] = __halves2half2(__float2half(v3.x), __float2half(v3.y));
    o[7] = __halves2half2(__float2half(v3.z), __float2half(v3.w));
    uint4* dst = (uint4*)(g_xh + (size_t)b * KDIM + j * 16);
    dst[0] = ((uint4*)o)[0];
    dst[1] = ((uint4*)o)[1];
}

// W1: pure streaming fp32->fp16 in native [t][k][n] layout, 8 floats/thread
__global__ void convert_w1_kernel(const float* __restrict__ W1) {
    const size_t i = ((size_t)blockIdx.x * 256 + threadIdx.x) * 8;
    float4 v0 = ((const float4*)(W1 + i))[0];
    float4 v1 = ((const float4*)(W1 + i))[1];
    __half2 o[4];
    o[0] = __halves2half2(__float2half(v0.x), __float2half(v0.y));
    o[1] = __halves2half2(__float2half(v0.z), __float2half(v0.w));
    o[2] = __halves2half2(__float2half(v1.x), __float2half(v1.y));
    o[3] = __halves2half2(__float2half(v1.z), __float2half(v1.w));
    *(uint4*)(g_w1h + i) = *(uint4*)o;
}

// W2: [t][k][100] -> [t][k][128] padded, fp16
__global__ void convert_w2_kernel(const float* __restrict__ W2) {
    const int rk = blockIdx.x;                   // t*1024 + k
    const int n  = threadIdx.x;                  // 0..127
    float v = (n < N_CLASSES) ? W2[(size_t)rk * N_CLASSES + n] : 0.f;
    g_w2h[(size_t)rk * 128 + n] = __float2half(v);
}

// ===================== GEMM core: BM x BN tile, K-chunks of 64 =====================
// A: [m][k] row-major (ldmatrix non-trans). B: [k][n] row-major (ldmatrix.trans).
// 8 warps: wm = wid&1 (BM/2 rows), wn = wid>>1 (BN/4 cols).
template<int BM, int BN, int BSTRIDE>
__device__ __forceinline__ void gemm_core(
    const __half* __restrict__ gA, const __half* __restrict__ gB,
    char* smem, float c[BM / 32][BN / 32][4])
{
    constexpr int MI = BM / 32, NI = BN / 32;
    constexpr int NCH = KDIM / 64;
    constexpr int A_BYTES = BM * LDSA * 2;
    constexpr int B_BYTES = 64 * LDSB * 2;
    constexpr int STAGE_B = A_BYTES + B_BYTES;
    constexpr int UNITS_A = BM * 8;              // 16B units per chunk
    constexpr int UNITS_B = 64 * (BN / 8);
    constexpr int UNITS = UNITS_A + UNITS_B;

    const int tid  = threadIdx.x;
    const int lane = tid & 31;
    const int wid  = tid >> 5;
    const int wm   = wid & 1;
    const int wn   = wid >> 1;
    const uint32_t smem0 = smem_u32(smem);

    // ldmatrix fragment addresses (bytes, within stage)
    uint32_t eA[MI], eB[NI / 2];
#pragma unroll
    for (int mi = 0; mi < MI; mi++)
        eA[mi] = ((wm * (BM / 2) + mi * 16 + (lane & 15)) * LDSA + (lane >> 4) * 8) * 2;
    {
        const int g = lane >> 3, r = lane & 7;
        const int kl = (g & 1) * 8 + r;
#pragma unroll
        for (int j = 0; j < NI / 2; j++)
            eB[j] = (kl * LDSB + wn * (BN / 4) + j * 16 + (g >> 1) * 8) * 2;
    }

    auto issue = [&](int ch, int stage) {
        const int k = ch * 64;
        const uint32_t dA = smem0 + stage * STAGE_B;
        const uint32_t dB = dA + A_BYTES;
#pragma unroll
        for (int u = tid; u < UNITS; u += 256) {
            if (u < UNITS_A) {
                int row = u >> 3, seg = u & 7;
                cp16(dA + (row * LDSA + seg * 8) * 2, gA + (size_t)row * KDIM + k + seg * 8);
            } else {
                int v = u - UNITS_A;
                int kr = v / (BN / 8), seg = v % (BN / 8);
                cp16(dB + (kr * LDSB + seg * 8) * 2, gB + (size_t)(k + kr) * BSTRIDE + seg * 8);
            }
        }
    };

    issue(0, 0); CP_COMMIT();
    issue(1, 1); CP_COMMIT();

    for (int ch = 0; ch < NCH; ch++) {
        CP_WAIT1();
        __syncthreads();
        if (ch + 2 < NCH) issue(ch + 2, (ch + 2) % STAGES);
        CP_COMMIT();

        const uint32_t bA = smem0 + (ch % STAGES) * STAGE_B;
        const uint32_t bB = bA + A_BYTES;
#pragma unroll
        for (int ks = 0; ks < 4; ks++) {
            uint32_t a[MI][4], b[NI][2];
#pragma unroll
            for (int mi = 0; mi < MI; mi++)
                ldm4(a[mi][0], a[mi][1], a[mi][2], a[mi][3], bA + eA[mi] + ks * 32);
#pragma unroll
            for (int j = 0; j < NI / 2; j++) {
                uint32_t r0, r1, r2, r3;
                ldm4t(r0, r1, r2, r3, bB + eB[j] + ks * (16 * LDSB * 2));
                b[2 * j][0] = r0; b[2 * j][1] = r1;
                b[2 * j + 1][0] = r2; b[2 * j + 1][1] = r3;
            }
#pragma unroll
            for (int mi = 0; mi < MI; mi++)
#pragma unroll
                for (int ni = 0; ni < NI; ni++)
                    mma16816(c[mi][ni], a[mi], b[ni]);
        }
    }
}

// ===================== layer 1: 128x128 tiles =====================
#define SMEM1 (STAGES * (128 * LDSA + 64 * LDSB) * 2)
__global__ __launch_bounds__(256, 2)
void gemm1_mma(const float* __restrict__ b1) {
    const int t   = blockIdx.z;
    const int cnt = g_count[t];
    const int m0  = blockIdx.y * 128;
    if (m0 >= cnt) return;
    const int off = g_offset[t];
    const int n0  = blockIdx.x * 128;

    extern __shared__ char smem[];
    float c[4][4][4];
#pragma unroll
    for (int mi = 0; mi < 4; mi++)
#pragma unroll
        for (int ni = 0; ni < 4; ni++)
#pragma unroll
            for (int r = 0; r < 4; r++) c[mi][ni][r] = 0.f;

    gemm_core<128, 128, HIDDEN>(g_xh + (size_t)(off + m0) * KDIM,
                                g_w1h + (size_t)t * KDIM * HIDDEN + n0, smem, c);

    const int lane = threadIdx.x & 31;
    const int wid  = threadIdx.x >> 5;
    const int wm = wid & 1, wn = wid >> 1;
    const int r4 = lane >> 2, c2 = (lane & 3) * 2;
    const float* b1t = b1 + t * HIDDEN + n0;

#pragma unroll
    for (int mi = 0; mi < 4; mi++) {
#pragma unroll
        for (int half = 0; half < 2; half++) {
            const int m = m0 + wm * 64 + mi * 16 + r4 + half * 8;
            if (m < cnt) {
                const size_t rowo = (size_t)(off + m) * KDIM;
#pragma unroll
                for (int ni = 0; ni < 4; ni++) {
                    const int n = wn * 32 + ni * 8 + c2;
                    float v0 = fmaxf(c[mi][ni][half * 2 + 0] + b1t[n], 0.f);
                    float v1 = fmaxf(c[mi][ni][half * 2 + 1] + b1t[n + 1], 0.f);
                    *(__half2*)(g_hh + rowo + n0 + n) =
                        __halves2half2(__float2half(v0), __float2half(v1));
                }
            }
        }
    }
}

// ===================== layer 2: 32x128 tiles, direct store + bias =====================
#define SMEM2 (STAGES * (32 * LDSA + 64 * LDSB) * 2)
__global__ __launch_bounds__(256, 2)
void gemm2_mma(const float* __restrict__ b2, float* __restrict__ out) {
    const int t   = blockIdx.z;
    const int cnt = g_count[t];
    const int m0  = blockIdx.y * 32;
    if (m0 >= cnt) return;
    const int off = g_offset[t];

    extern __shared__ char smem[];
    float c[1][4][4];
#pragma unroll
    for (int ni = 0; ni < 4; ni++)
#pragma unroll
        for (int r = 0; r < 4; r++) c[0][ni][r] = 0.f;

    gemm_core<32, 128, 128>(g_hh + (size_t)(off + m0) * KDIM,
                            g_w2h + (size_t)t * KDIM * 128, smem, c);

    const int lane = threadIdx.x & 31;
    const int wid  = threadIdx.x >> 5;
    const int wm = wid & 1, wn = wid >> 1;
    const int r4 = lane >> 2, c2 = (lane & 3) * 2;
    const float* b2t = b2 + t * N_CLASSES;

#pragma unroll
    for (int half = 0; half < 2; half++) {
        const int m = m0 + wm * 16 + r4 + half * 8;
        if (m < cnt) {
            const int ro = g_rows[off + m];
            float* orow = out + (size_t)ro * N_CLASSES;
#pragma unroll
            for (int ni = 0; ni < 4; ni++) {
                const int n = wn * 32 + ni * 8 + c2;
                if (n < N_CLASSES)
                    orow[n] = c[0][ni][half * 2 + 0] + b2t[n];
                if (n + 1 < N_CLASSES)
                    orow[n + 1] = c[0][ni][half * 2 + 1] + b2t[n + 1];
            }
        }
    }
}

// ===================== launch =====================
extern "C" void kernel_launch(void* const* d_in, const int* in_sizes, int n_in,
                              void* d_out, int out_size) {
    const float* x       = (const float*)d_in[0];
    const int*   task_id = (const int*)d_in[1];
    const float* W1      = (const float*)d_in[2];
    const float* b1      = (const float*)d_in[3];
    const float* W2      = (const float*)d_in[4];
    const float* b2      = (const float*)d_in[5];
    float* out = (float*)d_out;

    static bool attr_done = false;
    if (!attr_done) {
        cudaFuncSetAttribute(gemm1_mma, cudaFuncAttributeMaxDynamicSharedMemorySize, SMEM1);
        cudaFuncSetAttribute(gemm2_mma, cudaFuncAttributeMaxDynamicSharedMemorySize, SMEM2);
        attr_done = true;
    }

    group_kernel<<<1, 1024>>>(task_id);
    convert_w1_kernel<<<N_TASKS * KDIM * HIDDEN / (256 * 8), 256>>>(W1);
    convert_w2_kernel<<<N_TASKS * KDIM, 128>>>(W2);
    convert_x_kernel<<<BATCH / 4, 256>>>(x);

    gemm1_mma<<<dim3(8, 64, 8), 256, SMEM1>>>(b1);
    gemm2_mma<<<dim3(1, 256, 8), 256, SMEM2>>>(b2, out);
}

// round 9
// speedup vs baseline: 6.6897x; 1.0875x over previous
#include <cuda_runtime.h>
#include <cuda_fp16.h>
#include <cstdint>

#define N_TASKS   8
#define D_MODEL   1024
#define HIDDEN    1024
#define N_CLASSES 100
#define BATCH     8192
#define KDIM      1024
#define LDSA      72            // A smem row stride (halves): 64 + 8
#define LDSB      136           // B smem row stride (halves): 128 + 8
#define STAGES    3
#define GRID1     296           // 148 SMs x 2 CTA/SM, persistent

// ===================== device scratch =====================
__device__ int g_count[N_TASKS], g_offset[N_TASKS];
__device__ __align__(16) int g_rows[BATCH];
__device__ int g_mt_task[80], g_mt_m0[80], g_nmt;   // gemm1 m-tile table
__device__ int g_tile_ctr;                           // dynamic tile counter
__device__ __align__(256) __half g_xh[(BATCH + 128) * KDIM];      // grouped x fp16 [m][k]
__device__ __align__(256) __half g_w1h[N_TASKS * KDIM * HIDDEN];  // W1 fp16 native [t][k][n]
__device__ __align__(256) __half g_w2h[N_TASKS * KDIM * 128];     // W2 fp16 [t][k][n pad]
__device__ __align__(256) __half g_hh[(BATCH + 128) * KDIM];      // grouped h fp16 [m][k]

// ===================== helpers =====================
__device__ __forceinline__ uint32_t smem_u32(const void* p) {
    uint32_t a;
    asm("{ .reg .u64 t; cvta.to.shared.u64 t, %1; cvt.u32.u64 %0, t; }" : "=r"(a) : "l"(p));
    return a;
}
__device__ __forceinline__ void ldm4(uint32_t& r0, uint32_t& r1, uint32_t& r2, uint32_t& r3,
                                     uint32_t addr) {
    asm volatile("ldmatrix.sync.aligned.m8n8.x4.shared.b16 {%0,%1,%2,%3}, [%4];"
                 : "=r"(r0), "=r"(r1), "=r"(r2), "=r"(r3) : "r"(addr));
}
__device__ __forceinline__ void ldm4t(uint32_t& r0, uint32_t& r1, uint32_t& r2, uint32_t& r3,
                                      uint32_t addr) {
    asm volatile("ldmatrix.sync.aligned.m8n8.x4.trans.shared.b16 {%0,%1,%2,%3}, [%4];"
                 : "=r"(r0), "=r"(r1), "=r"(r2), "=r"(r3) : "r"(addr));
}
__device__ __forceinline__ void mma16816(float* c, const uint32_t* a, const uint32_t* b) {
    asm volatile(
        "mma.sync.aligned.m16n8k16.row.col.f32.f16.f16.f32 "
        "{%0,%1,%2,%3}, {%4,%5,%6,%7}, {%8,%9}, {%0,%1,%2,%3};"
        : "+f"(c[0]), "+f"(c[1]), "+f"(c[2]), "+f"(c[3])
        : "r"(a[0]), "r"(a[1]), "r"(a[2]), "r"(a[3]), "r"(b[0]), "r"(b[1]));
}
__device__ __forceinline__ void cp16(uint32_t dst, const void* src) {
    asm volatile("cp.async.cg.shared.global [%0], [%1], 16;" :: "r"(dst), "l"(src) : "memory");
}
#define CP_COMMIT() asm volatile("cp.async.commit_group;" ::: "memory")
#define CP_WAIT1()  asm volatile("cp.async.wait_group 1;" ::: "memory")
#define CP_WAIT0()  asm volatile("cp.async.wait_group 0;" ::: "memory")

// ===================== grouping + tile table (one CTA) =====================
__global__ __launch_bounds__(1024)
void group_kernel(const int* __restrict__ task_id) {
    __shared__ int cnt[N_TASKS], offs[N_TASKS], cur[N_TASKS];
    const int tid = threadIdx.x;
    if (tid < N_TASKS) { cnt[tid] = 0; cur[tid] = 0; }
    __syncthreads();
    int ids[8];
#pragma unroll
    for (int i = 0; i < 8; i++) {
        ids[i] = task_id[tid * 8 + i];
        atomicAdd(&cnt[ids[i]], 1);
    }
    __syncthreads();
    if (tid == 0) {
        int a = 0, nm = 0;
        for (int t = 0; t < N_TASKS; t++) {
            offs[t] = a; g_offset[t] = a; g_count[t] = cnt[t];
            for (int m0 = 0; m0 < cnt[t]; m0 += 128) {
                g_mt_task[nm] = t; g_mt_m0[nm] = m0; nm++;
            }
            a += cnt[t];
        }
        g_nmt = nm;
        g_tile_ctr = 0;
    }
    __syncthreads();
#pragma unroll
    for (int i = 0; i < 8; i++) {
        int t = ids[i];
        int p = atomicAdd(&cur[t], 1);
        g_rows[offs[t] + p] = tid * 8 + i;
    }
}

// ===================== fused conversions: one kernel, 3 regions =====================
#define W1_BLKS 4096      // 8*1024*1024 floats / (256*8)
#define W2_BLKS 512       // 8*1024 rows * 128 out / (256*8)
#define X_BLKS  2048      // 8192 rows / 4
__global__ void convert_all(const float* __restrict__ x,
                            const float* __restrict__ W1,
                            const float* __restrict__ W2) {
    const int bid = blockIdx.x;
    const int tid = threadIdx.x;
    if (bid < W1_BLKS) {
        // W1: pure streaming, 8 floats/thread
        const size_t i = ((size_t)bid * 256 + tid) * 8;
        float4 v0 = ((const float4*)(W1 + i))[0];
        float4 v1 = ((const float4*)(W1 + i))[1];
        __half2 o[4];
        o[0] = __halves2half2(__float2half(v0.x), __float2half(v0.y));
        o[1] = __halves2half2(__float2half(v0.z), __float2half(v0.w));
        o[2] = __halves2half2(__float2half(v1.x), __float2half(v1.y));
        o[3] = __halves2half2(__float2half(v1.z), __float2half(v1.w));
        *(uint4*)(g_w1h + i) = *(uint4*)o;
    } else if (bid < W1_BLKS + W2_BLKS) {
        // W2: [rk][100] -> [rk][128] padded, 8 outputs/thread
        const size_t e = ((size_t)(bid - W1_BLKS) * 256 + tid) * 8;
        const int rk = (int)(e >> 7);
        const int n0 = (int)(e & 127);
        const float* src = W2 + (size_t)rk * N_CLASSES;
        __half2 o[4];
#pragma unroll
        for (int j = 0; j < 4; j++) {
            int na = n0 + 2 * j, nb = n0 + 2 * j + 1;
            float fa = (na < N_CLASSES) ? src[na] : 0.f;
            float fb = (nb < N_CLASSES) ? src[nb] : 0.f;
            o[j] = __halves2half2(__float2half(fa), __float2half(fb));
        }
        *(uint4*)(g_w2h + (size_t)rk * 128 + n0) = *(uint4*)o;
    } else {
        // x: gather 4 rows/block, 16 floats/thread
        const int lrow = tid >> 6;
        const int j    = tid & 63;
        const int b    = (bid - W1_BLKS - W2_BLKS) * 4 + lrow;
        const int r    = g_rows[b];
        const float* src = x + (size_t)r * D_MODEL + j * 16;
        float4 v0 = ((const float4*)src)[0];
        float4 v1 = ((const float4*)src)[1];
        float4 v2 = ((const float4*)src)[2];
        float4 v3 = ((const float4*)src)[3];
        __half2 o[8];
        o[0] = __halves2half2(__float2half(v0.x), __float2half(v0.y));
        o[1] = __halves2half2(__float2half(v0.z), __float2half(v0.w));
        o[2] = __halves2half2(__float2half(v1.x), __float2half(v1.y));
        o[3] = __halves2half2(__float2half(v1.z), __float2half(v1.w));
        o[4] = __halves2half2(__float2half(v2.x), __float2half(v2.y));
        o[5] = __halves2half2(__float2half(v2.z), __float2half(v2.w));
        o[6] = __halves2half2(__float2half(v3.x), __float2half(v3.y));
        o[7] = __halves2half2(__float2half(v3.z), __float2half(v3.w));
        uint4* dst = (uint4*)(g_xh + (size_t)b * KDIM + j * 16);
        dst[0] = ((uint4*)o)[0];
        dst[1] = ((uint4*)o)[1];
    }
}

// ===================== GEMM core: BM x BN tile, K-chunks of 64 =====================
template<int BM, int BN, int BSTRIDE>
__device__ __forceinline__ void gemm_core(
    const __half* __restrict__ gA, const __half* __restrict__ gB,
    char* smem, float c[BM / 32][BN / 32][4])
{
    constexpr int MI = BM / 32, NI = BN / 32;
    constexpr int NCH = KDIM / 64;
    constexpr int A_BYTES = BM * LDSA * 2;
    constexpr int B_BYTES = 64 * LDSB * 2;
    constexpr int STAGE_B = A_BYTES + B_BYTES;
    constexpr int UNITS_A = BM * 8;
    constexpr int UNITS_B = 64 * (BN / 8);
    constexpr int UNITS = UNITS_A + UNITS_B;

    const int tid  = threadIdx.x;
    const int lane = tid & 31;
    const int wid  = tid >> 5;
    const int wm   = wid & 1;
    const int wn   = wid >> 1;
    const uint32_t smem0 = smem_u32(smem);

    uint32_t eA[MI], eB[NI / 2];
#pragma unroll
    for (int mi = 0; mi < MI; mi++)
        eA[mi] = ((wm * (BM / 2) + mi * 16 + (lane & 15)) * LDSA + (lane >> 4) * 8) * 2;
    {
        const int g = lane >> 3, r = lane & 7;
        const int kl = (g & 1) * 8 + r;
#pragma unroll
        for (int j = 0; j < NI / 2; j++)
            eB[j] = (kl * LDSB + wn * (BN / 4) + j * 16 + (g >> 1) * 8) * 2;
    }

    auto issue = [&](int ch, int stage) {
        const int k = ch * 64;
        const uint32_t dA = smem0 + stage * STAGE_B;
        const uint32_t dB = dA + A_BYTES;
#pragma unroll
        for (int u = tid; u < UNITS; u += 256) {
            if (u < UNITS_A) {
                int row = u >> 3, seg = u & 7;
                cp16(dA + (row * LDSA + seg * 8) * 2, gA + (size_t)row * KDIM + k + seg * 8);
            } else {
                int v = u - UNITS_A;
                int kr = v / (BN / 8), seg = v % (BN / 8);
                cp16(dB + (kr * LDSB + seg * 8) * 2, gB + (size_t)(k + kr) * BSTRIDE + seg * 8);
            }
        }
    };

    issue(0, 0); CP_COMMIT();
    issue(1, 1); CP_COMMIT();

    for (int ch = 0; ch < NCH; ch++) {
        CP_WAIT1();
        __syncthreads();
        if (ch + 2 < NCH) issue(ch + 2, (ch + 2) % STAGES);
        CP_COMMIT();

        const uint32_t bA = smem0 + (ch % STAGES) * STAGE_B;
        const uint32_t bB = bA + A_BYTES;
#pragma unroll
        for (int ks = 0; ks < 4; ks++) {
            uint32_t a[MI][4], b[NI][2];
#pragma unroll
            for (int mi = 0; mi < MI; mi++)
                ldm4(a[mi][0], a[mi][1], a[mi][2], a[mi][3], bA + eA[mi] + ks * 32);
#pragma unroll
            for (int j = 0; j < NI / 2; j++) {
                uint32_t r0, r1, r2, r3;
                ldm4t(r0, r1, r2, r3, bB + eB[j] + ks * (16 * LDSB * 2));
                b[2 * j][0] = r0; b[2 * j][1] = r1;
                b[2 * j + 1][0] = r2; b[2 * j + 1][1] = r3;
            }
#pragma unroll
            for (int mi = 0; mi < MI; mi++)
#pragma unroll
                for (int ni = 0; ni < NI; ni++)
                    mma16816(c[mi][ni], a[mi], b[ni]);
        }
    }
}

// ===================== layer 1: persistent, dynamic tile queue =====================
#define SMEM1 (STAGES * (128 * LDSA + 64 * LDSB) * 2)
__global__ __launch_bounds__(256, 2)
void gemm1_mma(const float* __restrict__ b1) {
    extern __shared__ char smem[];
    __shared__ int s_tile;
    const int ntotal = g_nmt * 8;

    const int lane = threadIdx.x & 31;
    const int wid  = threadIdx.x >> 5;
    const int wm = wid & 1, wn = wid >> 1;
    const int r4 = lane >> 2, c2 = (lane & 3) * 2;

    for (;;) {
        if (threadIdx.x == 0) s_tile = atomicAdd(&g_tile_ctr, 1);
        __syncthreads();
        const int tile = s_tile;
        if (tile >= ntotal) return;
        const int e  = tile >> 3;
        const int n0 = (tile & 7) * 128;
        const int t  = g_mt_task[e];
        const int m0 = g_mt_m0[e];
        const int cnt = g_count[t];
        const int off = g_offset[t];

        float c[4][4][4];
#pragma unroll
        for (int mi = 0; mi < 4; mi++)
#pragma unroll
            for (int ni = 0; ni < 4; ni++)
#pragma unroll
                for (int r = 0; r < 4; r++) c[mi][ni][r] = 0.f;

        gemm_core<128, 128, HIDDEN>(g_xh + (size_t)(off + m0) * KDIM,
                                    g_w1h + (size_t)t * KDIM * HIDDEN + n0, smem, c);

        const float* b1t = b1 + t * HIDDEN + n0;
#pragma unroll
        for (int mi = 0; mi < 4; mi++) {
#pragma unroll
            for (int half = 0; half < 2; half++) {
                const int m = m0 + wm * 64 + mi * 16 + r4 + half * 8;
                if (m < cnt) {
                    const size_t rowo = (size_t)(off + m) * KDIM;
#pragma unroll
                    for (int ni = 0; ni < 4; ni++) {
                        const int n = wn * 32 + ni * 8 + c2;
                        float v0 = fmaxf(c[mi][ni][half * 2 + 0] + b1t[n], 0.f);
                        float v1 = fmaxf(c[mi][ni][half * 2 + 1] + b1t[n + 1], 0.f);
                        *(__half2*)(g_hh + rowo + n0 + n) =
                            __halves2half2(__float2half(v0), __float2half(v1));
                    }
                }
            }
        }
        CP_WAIT0();
        __syncthreads();
    }
}

// ===================== layer 2: 32x128 tiles, direct store + bias =====================
#define SMEM2 (STAGES * (32 * LDSA + 64 * LDSB) * 2)
__global__ __launch_bounds__(256, 2)
void gemm2_mma(const float* __restrict__ b2, float* __restrict__ out) {
    const int t   = blockIdx.z;
    const int cnt = g_count[t];
    const int m0  = blockIdx.y * 32;
    if (m0 >= cnt) return;
    const int off = g_offset[t];

    extern __shared__ char smem[];
    float c[1][4][4];
#pragma unroll
    for (int ni = 0; ni < 4; ni++)
#pragma unroll
        for (int r = 0; r < 4; r++) c[0][ni][r] = 0.f;

    gemm_core<32, 128, 128>(g_hh + (size_t)(off + m0) * KDIM,
                            g_w2h + (size_t)t * KDIM * 128, smem, c);

    const int lane = threadIdx.x & 31;
    const int wid  = threadIdx.x >> 5;
    const int wm = wid & 1, wn = wid >> 1;
    const int r4 = lane >> 2, c2 = (lane & 3) * 2;
    const float* b2t = b2 + t * N_CLASSES;

#pragma unroll
    for (int half = 0; half < 2; half++) {
        const int m = m0 + wm * 16 + r4 + half * 8;
        if (m < cnt) {
            const int ro = g_rows[off + m];
            float* orow = out + (size_t)ro * N_CLASSES;
#pragma unroll
            for (int ni = 0; ni < 4; ni++) {
                const int n = wn * 32 + ni * 8 + c2;
                if (n < N_CLASSES)
                    orow[n] = c[0][ni][half * 2 + 0] + b2t[n];
                if (n + 1 < N_CLASSES)
                    orow[n + 1] = c[0][ni][half * 2 + 1] + b2t[n + 1];
            }
        }
    }
}

// ===================== launch =====================
extern "C" void kernel_launch(void* const* d_in, const int* in_sizes, int n_in,
                              void* d_out, int out_size) {
    const float* x       = (const float*)d_in[0];
    const int*   task_id = (const int*)d_in[1];
    const float* W1      = (const float*)d_in[2];
    const float* b1      = (const float*)d_in[3];
    const float* W2      = (const float*)d_in[4];
    const float* b2      = (const float*)d_in[5];
    float* out = (float*)d_out;

    static bool attr_done = false;
    if (!attr_done) {
        cudaFuncSetAttribute(gemm1_mma, cudaFuncAttributeMaxDynamicSharedMemorySize, SMEM1);
        cudaFuncSetAttribute(gemm2_mma, cudaFuncAttributeMaxDynamicSharedMemorySize, SMEM2);
        attr_done = true;
    }

    group_kernel<<<1, 1024>>>(task_id);
    convert_all<<<W1_BLKS + W2_BLKS + X_BLKS, 256>>>(x, W1, W2);

    gemm1_mma<<<GRID1, 256, SMEM1>>>(b1);
    gemm2_mma<<<dim3(1, 256, 8), 256, SMEM2>>>(b2, out);
}